// round 1
// baseline (speedup 1.0000x reference)
#include <cuda_runtime.h>
#include <math.h>

#define T_TOK   8192      // B*S
#define DMODEL  512
#define FF      2048
#define NE      8
#define TOPK    2

#define BM 64
#define BN 64
#define BK 16
#define PAD 4             // smem pad (keeps float4 alignment: stride 68 floats = 272B)

#define ROWS_MAX (TOPK*T_TOK + NE*BM)   // 16384 + 512 = 16896 (padded row space)

// ---------------- scratch (static device allocations; no cudaMalloc) ----------
__device__ float g_hidden[(size_t)ROWS_MAX * FF];   // ~138 MB
__device__ int   g_row_tok[ROWS_MAX];
__device__ float g_row_w[ROWS_MAX];
__device__ int   g_tok_e[T_TOK * TOPK];
__device__ float g_tok_w[T_TOK * TOPK];
__device__ int   g_cnt[NE];
__device__ int   g_cur[NE];
__device__ int   g_pofs[NE + 1];

// ---------------- init: zero counters, row arrays, output -----------------
__global__ void init_kernel(float* __restrict__ out, int out_n) {
    int i = blockIdx.x * blockDim.x + threadIdx.x;
    if (i < NE) { g_cnt[i] = 0; g_cur[i] = 0; }
    if (i < ROWS_MAX) { g_row_tok[i] = 0; g_row_w[i] = 0.f; }
    int stride = gridDim.x * blockDim.x;
    for (int j = i; j < out_n; j += stride) out[j] = 0.f;
}

// ---------------- router: warp per token, top-2 of 8, softmax cancels ------
__global__ void router_kernel(const float* __restrict__ x,
                              const float* __restrict__ rw,
                              const float* __restrict__ rb) {
    int gtid = blockIdx.x * blockDim.x + threadIdx.x;
    int t    = gtid >> 5;
    int lane = gtid & 31;
    if (t >= T_TOK) return;

    const float* xr = x + (size_t)t * DMODEL;
    float acc[NE];
#pragma unroll
    for (int e = 0; e < NE; e++) acc[e] = 0.f;

    for (int d = lane; d < DMODEL; d += 32) {
        float xv = xr[d];
        const float* r = rw + d * NE;
#pragma unroll
        for (int e = 0; e < NE; e++) acc[e] = fmaf(xv, r[e], acc[e]);
    }
#pragma unroll
    for (int off = 16; off > 0; off >>= 1) {
#pragma unroll
        for (int e = 0; e < NE; e++)
            acc[e] += __shfl_down_sync(0xffffffffu, acc[e], off);
    }
    if (lane == 0) {
        float best = -1e30f, second = -1e30f;
        int b0 = 0, b1 = 0;
#pragma unroll
        for (int e = 0; e < NE; e++) {
            float l = acc[e] + rb[e];
            if (l > best)        { second = best; b1 = b0; best = l; b0 = e; }
            else if (l > second) { second = l; b1 = e; }
        }
        // normalized top-2 weights; softmax denominator cancels
        float w0 = 1.f / (1.f + __expf(second - best));
        float w1 = 1.f - w0;
        g_tok_e[2 * t + 0] = b0;  g_tok_w[2 * t + 0] = w0;
        g_tok_e[2 * t + 1] = b1;  g_tok_w[2 * t + 1] = w1;
        atomicAdd(&g_cnt[b0], 1);
        atomicAdd(&g_cnt[b1], 1);
    }
}

// ---------------- offsets: BM-aligned per-expert segments ------------------
__global__ void offsets_kernel() {
    int o = 0;
    for (int e = 0; e < NE; e++) {
        g_pofs[e] = o;
        o += ((g_cnt[e] + BM - 1) / BM) * BM;
    }
    g_pofs[NE] = o;
}

// ---------------- scatter tokens into expert segments ----------------------
__global__ void scatter_kernel() {
    int t = blockIdx.x * blockDim.x + threadIdx.x;
    if (t >= T_TOK) return;
#pragma unroll
    for (int k = 0; k < TOPK; k++) {
        int   e = g_tok_e[2 * t + k];
        float w = g_tok_w[2 * t + k];
        int pos = g_pofs[e] + atomicAdd(&g_cur[e], 1);
        g_row_tok[pos] = t;
        g_row_w[pos]   = w;
    }
}

// ---------------- GEMM1: hidden = relu(gather(x) @ w1[e] + b1[e]) ---------
__global__ __launch_bounds__(256)
void ffn1_kernel(const float* __restrict__ x,
                 const float* __restrict__ w1,
                 const float* __restrict__ b1) {
    __shared__ float As[BK][BM + PAD];
    __shared__ float Bs[BK][BN + PAD];
    __shared__ int   toks[BM];

    int r0 = blockIdx.x * BM;
    if (r0 >= g_pofs[NE]) return;
    int e = 0;
    while (r0 >= g_pofs[e + 1]) e++;

    int tid = threadIdx.x;
    if (tid < BM) toks[tid] = g_row_tok[r0 + tid];
    __syncthreads();

    const float* W = w1 + (size_t)e * DMODEL * FF;
    int n0 = blockIdx.y * BN;

    int tx = tid & 15, ty = tid >> 4;           // 16 x 16 thread tile
    int a_m = tid >> 2, a_k = (tid & 3) * 4;    // A load: 64 rows x 16 k
    int b_k = tid >> 4, b_n = (tid & 15) * 4;   // B load: 16 k  x 64 n

    float acc[4][4];
#pragma unroll
    for (int i = 0; i < 4; i++)
#pragma unroll
        for (int j = 0; j < 4; j++) acc[i][j] = 0.f;

    for (int k0 = 0; k0 < DMODEL; k0 += BK) {
        float4 av = *(const float4*)(x + (size_t)toks[a_m] * DMODEL + k0 + a_k);
        As[a_k + 0][a_m] = av.x;
        As[a_k + 1][a_m] = av.y;
        As[a_k + 2][a_m] = av.z;
        As[a_k + 3][a_m] = av.w;
        *(float4*)&Bs[b_k][b_n] =
            *(const float4*)(W + (size_t)(k0 + b_k) * FF + n0 + b_n);
        __syncthreads();
#pragma unroll
        for (int kk = 0; kk < BK; kk++) {
            float4 a4 = *(const float4*)&As[kk][ty * 4];
            float4 b4 = *(const float4*)&Bs[kk][tx * 4];
            float av_[4] = {a4.x, a4.y, a4.z, a4.w};
            float bv_[4] = {b4.x, b4.y, b4.z, b4.w};
#pragma unroll
            for (int i = 0; i < 4; i++)
#pragma unroll
                for (int j = 0; j < 4; j++)
                    acc[i][j] = fmaf(av_[i], bv_[j], acc[i][j]);
        }
        __syncthreads();
    }

    float4 bb = *(const float4*)(b1 + (size_t)e * FF + n0 + tx * 4);
#pragma unroll
    for (int i = 0; i < 4; i++) {
        int m = ty * 4 + i;
        float4 v;
        v.x = fmaxf(acc[i][0] + bb.x, 0.f);
        v.y = fmaxf(acc[i][1] + bb.y, 0.f);
        v.z = fmaxf(acc[i][2] + bb.z, 0.f);
        v.w = fmaxf(acc[i][3] + bb.w, 0.f);
        *(float4*)(g_hidden + (size_t)(r0 + m) * FF + n0 + tx * 4) = v;
    }
}

// ---------------- GEMM2: out[tok] += w * (hidden @ w2[e] + b2[e]) ---------
__global__ __launch_bounds__(256)
void ffn2_kernel(const float* __restrict__ w2,
                 const float* __restrict__ b2,
                 float* __restrict__ out) {
    __shared__ float As[BK][BM + PAD];
    __shared__ float Bs[BK][BN + PAD];

    int r0 = blockIdx.x * BM;
    if (r0 >= g_pofs[NE]) return;
    int e = 0;
    while (r0 >= g_pofs[e + 1]) e++;

    const float* W = w2 + (size_t)e * FF * DMODEL;
    int n0 = blockIdx.y * BN;
    int tid = threadIdx.x;

    int tx = tid & 15, ty = tid >> 4;
    int a_m = tid >> 2, a_k = (tid & 3) * 4;
    int b_k = tid >> 4, b_n = (tid & 15) * 4;

    float acc[4][4];
#pragma unroll
    for (int i = 0; i < 4; i++)
#pragma unroll
        for (int j = 0; j < 4; j++) acc[i][j] = 0.f;

    for (int k0 = 0; k0 < FF; k0 += BK) {
        float4 av = *(const float4*)(g_hidden + (size_t)(r0 + a_m) * FF + k0 + a_k);
        As[a_k + 0][a_m] = av.x;
        As[a_k + 1][a_m] = av.y;
        As[a_k + 2][a_m] = av.z;
        As[a_k + 3][a_m] = av.w;
        *(float4*)&Bs[b_k][b_n] =
            *(const float4*)(W + (size_t)(k0 + b_k) * DMODEL + n0 + b_n);
        __syncthreads();
#pragma unroll
        for (int kk = 0; kk < BK; kk++) {
            float4 a4 = *(const float4*)&As[kk][ty * 4];
            float4 b4 = *(const float4*)&Bs[kk][tx * 4];
            float av_[4] = {a4.x, a4.y, a4.z, a4.w};
            float bv_[4] = {b4.x, b4.y, b4.z, b4.w};
#pragma unroll
            for (int i = 0; i < 4; i++)
#pragma unroll
                for (int j = 0; j < 4; j++)
                    acc[i][j] = fmaf(av_[i], bv_[j], acc[i][j]);
        }
        __syncthreads();
    }

    float4 bb = *(const float4*)(b2 + (size_t)e * DMODEL + n0 + tx * 4);
#pragma unroll
    for (int i = 0; i < 4; i++) {
        int r = r0 + ty * 4 + i;
        int   tok = g_row_tok[r];
        float w   = g_row_w[r];
        if (w != 0.f) {
            float* o = out + (size_t)tok * DMODEL + n0 + tx * 4;
            atomicAdd(&o[0], w * (acc[i][0] + bb.x));
            atomicAdd(&o[1], w * (acc[i][1] + bb.y));
            atomicAdd(&o[2], w * (acc[i][2] + bb.z));
            atomicAdd(&o[3], w * (acc[i][3] + bb.w));
        }
    }
}

// ---------------------------------------------------------------------------
extern "C" void kernel_launch(void* const* d_in, const int* in_sizes, int n_in,
                              void* d_out, int out_size) {
    const float* x        = (const float*)d_in[0];
    const float* router_w = (const float*)d_in[1];
    const float* router_b = (const float*)d_in[2];
    const float* w1       = (const float*)d_in[3];
    const float* b1       = (const float*)d_in[4];
    const float* w2       = (const float*)d_in[5];
    const float* b2       = (const float*)d_in[6];
    float* out            = (float*)d_out;

    (void)in_sizes; (void)n_in;

    init_kernel<<<132, 256>>>(out, out_size);

    // router: warp per token -> 8192 warps = 1024 blocks of 8 warps
    router_kernel<<<(T_TOK * 32 + 255) / 256, 256>>>(x, router_w, router_b);

    offsets_kernel<<<1, 1>>>();

    scatter_kernel<<<(T_TOK + 255) / 256, 256>>>();

    dim3 g1(ROWS_MAX / BM, FF / BN);       // 264 x 32
    ffn1_kernel<<<g1, 256>>>(x, w1, b1);

    dim3 g2(ROWS_MAX / BM, DMODEL / BN);   // 264 x 8
    ffn2_kernel<<<g2, 256>>>(w2, b2, out);
}

// round 3
// speedup vs baseline: 1.9610x; 1.9610x over previous
#include <cuda_runtime.h>
#include <cstdint>
#include <math.h>

#define T_TOK   8192
#define DMODEL  512
#define FF      2048
#define NE      8
#define TOPK    2

#define BM 128
#define BN 128
#define BK 32
#define ROWS_MAX (TOPK*T_TOK + NE*BM)   // 16384 + 1024 = 17408

// ---------------- static device scratch (no cudaMalloc allowed) -------------
__device__ float g_hidden[(size_t)ROWS_MAX * FF];     // ~142 MB
__device__ float g_eout[(size_t)ROWS_MAX * DMODEL];   // ~36 MB
__device__ int   g_row_tok[ROWS_MAX];
__device__ int   g_tok_e[T_TOK * TOPK];
__device__ int   g_tok_slot[T_TOK * TOPK];
__device__ float g_tok_w[T_TOK * TOPK];
__device__ int   g_cnt[NE];
__device__ int   g_cur[NE];
__device__ int   g_pofs[NE + 1];

// ---------------- helpers ---------------------------------------------------
__device__ __forceinline__ uint32_t smem_u32(const void* p) {
    uint32_t a;
    asm("{ .reg .u64 t; cvta.to.shared.u64 t, %1; cvt.u32.u64 %0, t; }" : "=r"(a) : "l"(p));
    return a;
}
__device__ __forceinline__ void cp16(uint32_t dst, const void* src) {
    asm volatile("cp.async.cg.shared.global [%0], [%1], 16;" :: "r"(dst), "l"(src));
}
#define CP_COMMIT() asm volatile("cp.async.commit_group;" ::: "memory")
__device__ __forceinline__ uint32_t f2tf(float f) {
    uint32_t u;
    asm("cvt.rna.tf32.f32 %0, %1;" : "=r"(u) : "f"(f));
    return u;
}
__device__ __forceinline__ void mma_tf32(float& c0, float& c1, float& c2, float& c3,
                                         uint32_t a0, uint32_t a1, uint32_t a2, uint32_t a3,
                                         uint32_t b0, uint32_t b1) {
    asm volatile(
        "mma.sync.aligned.m16n8k8.row.col.f32.tf32.tf32.f32 "
        "{%0,%1,%2,%3}, {%4,%5,%6,%7}, {%8,%9}, {%0,%1,%2,%3};"
        : "+f"(c0), "+f"(c1), "+f"(c2), "+f"(c3)
        : "r"(a0), "r"(a1), "r"(a2), "r"(a3), "r"(b0), "r"(b1));
}

// ---------------- init ------------------------------------------------------
__global__ void init_kernel() {
    int i = blockIdx.x * blockDim.x + threadIdx.x;
    if (i < NE) { g_cnt[i] = 0; g_cur[i] = 0; }
    if (i < ROWS_MAX) g_row_tok[i] = 0;
}

// ---------------- router: warp per token, top-2 of 8 ------------------------
__global__ void router_kernel(const float* __restrict__ x,
                              const float* __restrict__ rw,
                              const float* __restrict__ rb) {
    int gtid = blockIdx.x * blockDim.x + threadIdx.x;
    int t = gtid >> 5, lane = gtid & 31;
    if (t >= T_TOK) return;
    const float* xr = x + (size_t)t * DMODEL;
    float acc[NE];
#pragma unroll
    for (int e = 0; e < NE; e++) acc[e] = 0.f;
    for (int d = lane; d < DMODEL; d += 32) {
        float xv = xr[d];
        const float* r = rw + d * NE;
#pragma unroll
        for (int e = 0; e < NE; e++) acc[e] = fmaf(xv, r[e], acc[e]);
    }
#pragma unroll
    for (int off = 16; off > 0; off >>= 1)
#pragma unroll
        for (int e = 0; e < NE; e++)
            acc[e] += __shfl_down_sync(0xffffffffu, acc[e], off);
    if (lane == 0) {
        float best = -1e30f, second = -1e30f;
        int b0 = 0, b1 = 0;
#pragma unroll
        for (int e = 0; e < NE; e++) {
            float l = acc[e] + rb[e];
            if (l > best)        { second = best; b1 = b0; best = l; b0 = e; }
            else if (l > second) { second = l; b1 = e; }
        }
        float w0 = 1.f / (1.f + __expf(second - best));
        g_tok_e[2*t+0] = b0;  g_tok_w[2*t+0] = w0;
        g_tok_e[2*t+1] = b1;  g_tok_w[2*t+1] = 1.f - w0;
        atomicAdd(&g_cnt[b0], 1);
        atomicAdd(&g_cnt[b1], 1);
    }
}

// ---------------- offsets (BM-aligned per-expert segments) ------------------
__global__ void offsets_kernel() {
    int o = 0;
    for (int e = 0; e < NE; e++) {
        g_pofs[e] = o;
        o += ((g_cnt[e] + BM - 1) / BM) * BM;
    }
    g_pofs[NE] = o;
}

// ---------------- scatter ---------------------------------------------------
__global__ void scatter_kernel() {
    int t = blockIdx.x * blockDim.x + threadIdx.x;
    if (t >= T_TOK) return;
#pragma unroll
    for (int k = 0; k < TOPK; k++) {
        int e = g_tok_e[2*t+k];
        int pos = g_pofs[e] + atomicAdd(&g_cur[e], 1);
        g_row_tok[pos] = t;
        g_tok_slot[2*t+k] = pos;
    }
}

// ---------------- grouped tf32 mma.sync GEMM --------------------------------
// C[128x128] = A[128 x KD] @ W_e[KD x NTOT] (W is K-major row-major = .col B)
// 3-stage cp.async pipeline, 8 warps (2m x 4n), m16n8k8 tf32.

#define A_STRIDE 36          // floats per A smem row (pad 4)
#define B_STRIDE 136         // floats per B smem row (pad 8)
#define A_BUF_BYTES (BM * A_STRIDE * 4)          // 18432
#define B_BUF_BYTES (BK * B_STRIDE * 4)          // 17408
#define SM_B_BASE   (3 * A_BUF_BYTES)            // 55296
#define SM_TOKS     (SM_B_BASE + 3 * B_BUF_BYTES)  // 107520
#define SMEM_TOTAL  (SM_TOKS + BM * 4)           // 108032

template<int KD, int NTOT, bool GATHER, bool RELU>
__global__ __launch_bounds__(256, 1)
void ffn_mma(const float* __restrict__ Asrc,
             const float* __restrict__ W,
             const float* __restrict__ bias,
             float* __restrict__ Out) {
    extern __shared__ __align__(128) char smem[];
    const int tid  = threadIdx.x;
    const int wid  = tid >> 5;
    const int lane = tid & 31;
    const int qid  = lane >> 2;   // 0..7
    const int rid  = lane & 3;    // 0..3
    const int wm   = wid >> 2;    // 0..1 (64 rows each)
    const int wn   = wid & 3;     // 0..3 (32 cols each)

    const int r0 = blockIdx.x * BM;
    if (r0 >= g_pofs[NE]) return;
    int e = 0;
    while (r0 >= g_pofs[e + 1]) e++;

    const uint32_t sb = smem_u32(smem);
    int* toks = (int*)(smem + SM_TOKS);
    if (GATHER) {
        if (tid < BM) toks[tid] = g_row_tok[r0 + tid];
        __syncthreads();
    }

    const float* We = W + (size_t)e * KD * NTOT;
    const int n0 = blockIdx.y * BN;

    // per-thread copy geometry (4 chunks of 16B for A, 4 for B per tile)
    const float* aptr[4];
    uint32_t     aoff[4];
    const float* bptr[4];
    uint32_t     boff[4];
#pragma unroll
    for (int t = 0; t < 4; t++) {
        int id  = tid + t * 256;
        int ar  = id >> 3, ac = id & 7;              // row 0..127, 16B chunk 0..7
        aptr[t] = (GATHER ? Asrc + (size_t)toks[ar] * KD
                          : Asrc + (size_t)(r0 + ar) * KD) + ac * 4;
        aoff[t] = (uint32_t)(ar * (A_STRIDE * 4) + ac * 16);
        int bk  = id >> 5, bc = id & 31;             // k-row 0..31, chunk 0..31
        bptr[t] = We + (size_t)bk * NTOT + n0 + bc * 4;
        boff[t] = (uint32_t)(SM_B_BASE + bk * (B_STRIDE * 4) + bc * 16);
    }

    float acc[4][4][4];
#pragma unroll
    for (int i = 0; i < 4; i++)
#pragma unroll
        for (int j = 0; j < 4; j++)
#pragma unroll
            for (int k = 0; k < 4; k++) acc[i][j][k] = 0.f;

    const int NIT = KD / BK;

    // prologue: stage 0 and 1
#pragma unroll
    for (int s = 0; s < 2; s++) {
#pragma unroll
        for (int t = 0; t < 4; t++) {
            cp16(sb + aoff[t] + s * A_BUF_BYTES, aptr[t] + s * BK);
            cp16(sb + boff[t] + s * B_BUF_BYTES, bptr[t] + (size_t)s * BK * NTOT);
        }
        CP_COMMIT();
    }

    for (int it = 0; it < NIT; it++) {
        int cur = it % 3;
        if (it + 2 < NIT) {
            int nxt = (it + 2) % 3;
            int k0 = (it + 2) * BK;
#pragma unroll
            for (int t = 0; t < 4; t++) {
                cp16(sb + aoff[t] + nxt * A_BUF_BYTES, aptr[t] + k0);
                cp16(sb + boff[t] + nxt * B_BUF_BYTES, bptr[t] + (size_t)k0 * NTOT);
            }
            CP_COMMIT();
            asm volatile("cp.async.wait_group 2;" ::: "memory");
        } else if (it + 1 < NIT) {
            asm volatile("cp.async.wait_group 1;" ::: "memory");
        } else {
            asm volatile("cp.async.wait_group 0;" ::: "memory");
        }
        __syncthreads();

        const float* As = (const float*)(smem + cur * A_BUF_BYTES);
        const float* Bs = (const float*)(smem + SM_B_BASE + cur * B_BUF_BYTES);
#pragma unroll
        for (int ks = 0; ks < BK / 8; ks++) {
            const int kk = ks * 8;
            uint32_t a[4][4], b[4][2];
#pragma unroll
            for (int mt = 0; mt < 4; mt++) {
                int row = wm * 64 + mt * 16 + qid;
                a[mt][0] = f2tf(As[row * A_STRIDE + kk + rid]);
                a[mt][1] = f2tf(As[(row + 8) * A_STRIDE + kk + rid]);
                a[mt][2] = f2tf(As[row * A_STRIDE + kk + rid + 4]);
                a[mt][3] = f2tf(As[(row + 8) * A_STRIDE + kk + rid + 4]);
            }
#pragma unroll
            for (int nt = 0; nt < 4; nt++) {
                int col = wn * 32 + nt * 8 + qid;
                b[nt][0] = f2tf(Bs[(kk + rid) * B_STRIDE + col]);
                b[nt][1] = f2tf(Bs[(kk + rid + 4) * B_STRIDE + col]);
            }
#pragma unroll
            for (int mt = 0; mt < 4; mt++)
#pragma unroll
                for (int nt = 0; nt < 4; nt++)
                    mma_tf32(acc[mt][nt][0], acc[mt][nt][1], acc[mt][nt][2], acc[mt][nt][3],
                             a[mt][0], a[mt][1], a[mt][2], a[mt][3],
                             b[nt][0], b[nt][1]);
        }
        __syncthreads();
    }

    // epilogue: c0,c1 -> (row, col..col+1); c2,c3 -> (row+8, ...)
    const float* be = bias + (size_t)e * NTOT + n0;
#pragma unroll
    for (int mt = 0; mt < 4; mt++) {
        int row = r0 + wm * 64 + mt * 16 + qid;
#pragma unroll
        for (int nt = 0; nt < 4; nt++) {
            int col = wn * 32 + nt * 8 + 2 * rid;
            float2 bv = *(const float2*)(be + col);
            float2 v0, v1;
            v0.x = acc[mt][nt][0] + bv.x;
            v0.y = acc[mt][nt][1] + bv.y;
            v1.x = acc[mt][nt][2] + bv.x;
            v1.y = acc[mt][nt][3] + bv.y;
            if (RELU) {
                v0.x = fmaxf(v0.x, 0.f); v0.y = fmaxf(v0.y, 0.f);
                v1.x = fmaxf(v1.x, 0.f); v1.y = fmaxf(v1.y, 0.f);
            }
            *(float2*)(Out + (size_t)row * NTOT + n0 + col)       = v0;
            *(float2*)(Out + (size_t)(row + 8) * NTOT + n0 + col) = v1;
        }
    }
}

// ---------------- combine: out[t] = w0*eout[s0] + w1*eout[s1] ---------------
__global__ void combine_kernel(float* __restrict__ out) {
    int gid = blockIdx.x * blockDim.x + threadIdx.x;
    int t = gid >> 7;
    int j = (gid & 127) * 4;
    if (t >= T_TOK) return;
    int s0 = g_tok_slot[2*t], s1 = g_tok_slot[2*t+1];
    float w0 = g_tok_w[2*t], w1 = g_tok_w[2*t+1];
    float4 a = *(const float4*)(g_eout + (size_t)s0 * DMODEL + j);
    float4 b = *(const float4*)(g_eout + (size_t)s1 * DMODEL + j);
    float4 o;
    o.x = w0 * a.x + w1 * b.x;
    o.y = w0 * a.y + w1 * b.y;
    o.z = w0 * a.z + w1 * b.z;
    o.w = w0 * a.w + w1 * b.w;
    *(float4*)(out + (size_t)t * DMODEL + j) = o;
}

// ---------------------------------------------------------------------------
extern "C" void kernel_launch(void* const* d_in, const int* in_sizes, int n_in,
                              void* d_out, int out_size) {
    const float* x        = (const float*)d_in[0];
    const float* router_w = (const float*)d_in[1];
    const float* router_b = (const float*)d_in[2];
    const float* w1       = (const float*)d_in[3];
    const float* b1       = (const float*)d_in[4];
    const float* w2       = (const float*)d_in[5];
    const float* b2       = (const float*)d_in[6];
    float* out            = (float*)d_out;
    (void)in_sizes; (void)n_in; (void)out_size;

    float* hid; cudaGetSymbolAddress((void**)&hid, g_hidden);
    float* eo;  cudaGetSymbolAddress((void**)&eo,  g_eout);

    cudaFuncSetAttribute(ffn_mma<DMODEL, FF, true,  true >,
                         cudaFuncAttributeMaxDynamicSharedMemorySize, SMEM_TOTAL);
    cudaFuncSetAttribute(ffn_mma<FF, DMODEL, false, false>,
                         cudaFuncAttributeMaxDynamicSharedMemorySize, SMEM_TOTAL);

    init_kernel<<<(ROWS_MAX + 255) / 256, 256>>>();
    router_kernel<<<(T_TOK * 32 + 255) / 256, 256>>>(x, router_w, router_b);
    offsets_kernel<<<1, 1>>>();
    scatter_kernel<<<(T_TOK + 255) / 256, 256>>>();

    dim3 g1(ROWS_MAX / BM, FF / BN);       // 136 x 16
    ffn_mma<DMODEL, FF, true, true><<<g1, 256, SMEM_TOTAL>>>(x, w1, b1, hid);

    dim3 g2(ROWS_MAX / BM, DMODEL / BN);   // 136 x 4
    ffn_mma<FF, DMODEL, false, false><<<g2, 256, SMEM_TOTAL>>>(hid, w2, b2, eo);

    combine_kernel<<<(T_TOK * 128 + 255) / 256, 256>>>(out);
}

// round 4
// speedup vs baseline: 3.0499x; 1.5553x over previous
#include <cuda_runtime.h>
#include <cstdint>
#include <math.h>

#define T_TOK   8192
#define DMODEL  512
#define FF      2048
#define NE      8
#define TOPK    2

#define BM 128
#define BN 128
#define BK 32
#define ROWS_MAX (TOPK*T_TOK + NE*BM)   // 17408

// ---------------- static device scratch (no cudaMalloc allowed) -------------
__device__ float g_hidden[(size_t)ROWS_MAX * FF];     // ~142 MB (tf32-rounded)
__device__ float g_eout[(size_t)ROWS_MAX * DMODEL];   // ~36 MB
__device__ float g_xr[(size_t)T_TOK * DMODEL];        // tf32-rounded x
__device__ float g_w1r[(size_t)NE * DMODEL * FF];     // tf32-rounded w1
__device__ float g_w2r[(size_t)NE * FF * DMODEL];     // tf32-rounded w2
__device__ int   g_row_tok[ROWS_MAX];
__device__ int   g_tok_e[T_TOK * TOPK];
__device__ int   g_tok_slot[T_TOK * TOPK];
__device__ float g_tok_w[T_TOK * TOPK];
__device__ int   g_cnt[NE];
__device__ int   g_cur[NE];
__device__ int   g_pofs[NE + 1];

// ---------------- helpers ---------------------------------------------------
__device__ __forceinline__ uint32_t smem_u32(const void* p) {
    uint32_t a;
    asm("{ .reg .u64 t; cvta.to.shared.u64 t, %1; cvt.u32.u64 %0, t; }" : "=r"(a) : "l"(p));
    return a;
}
__device__ __forceinline__ void cp16(uint32_t dst, const void* src) {
    asm volatile("cp.async.cg.shared.global [%0], [%1], 16;" :: "r"(dst), "l"(src));
}
#define CP_COMMIT() asm volatile("cp.async.commit_group;" ::: "memory")
__device__ __forceinline__ uint32_t f2tf(float f) {
    uint32_t u;
    asm("cvt.rna.tf32.f32 %0, %1;" : "=r"(u) : "f"(f));
    return u;
}
__device__ __forceinline__ void ldsm_x4(uint32_t& r0, uint32_t& r1, uint32_t& r2, uint32_t& r3,
                                        uint32_t addr) {
    asm volatile("ldmatrix.sync.aligned.m8n8.x4.shared.b16 {%0,%1,%2,%3}, [%4];"
                 : "=r"(r0), "=r"(r1), "=r"(r2), "=r"(r3) : "r"(addr));
}
__device__ __forceinline__ void mma_tf32(float& c0, float& c1, float& c2, float& c3,
                                         uint32_t a0, uint32_t a1, uint32_t a2, uint32_t a3,
                                         uint32_t b0, uint32_t b1) {
    asm volatile(
        "mma.sync.aligned.m16n8k8.row.col.f32.tf32.tf32.f32 "
        "{%0,%1,%2,%3}, {%4,%5,%6,%7}, {%8,%9}, {%0,%1,%2,%3};"
        : "+f"(c0), "+f"(c1), "+f"(c2), "+f"(c3)
        : "r"(a0), "r"(a1), "r"(a2), "r"(a3), "r"(b0), "r"(b1));
}

// ---------------- init ------------------------------------------------------
__global__ void init_kernel() {
    int i = blockIdx.x * blockDim.x + threadIdx.x;
    if (i < NE) { g_cnt[i] = 0; g_cur[i] = 0; }
    if (i < ROWS_MAX) g_row_tok[i] = 0;
}

// ---------------- elementwise tf32 pre-rounding -----------------------------
__global__ void round_kernel(const float* __restrict__ src, float* __restrict__ dst,
                             int n4) {
    int i = blockIdx.x * blockDim.x + threadIdx.x;
    int stride = gridDim.x * blockDim.x;
    for (; i < n4; i += stride) {
        float4 v = ((const float4*)src)[i];
        v.x = __uint_as_float(f2tf(v.x));
        v.y = __uint_as_float(f2tf(v.y));
        v.z = __uint_as_float(f2tf(v.z));
        v.w = __uint_as_float(f2tf(v.w));
        ((float4*)dst)[i] = v;
    }
}

// ---------------- router ----------------------------------------------------
__global__ void router_kernel(const float* __restrict__ x,
                              const float* __restrict__ rw,
                              const float* __restrict__ rb) {
    int gtid = blockIdx.x * blockDim.x + threadIdx.x;
    int t = gtid >> 5, lane = gtid & 31;
    if (t >= T_TOK) return;
    const float* xr = x + (size_t)t * DMODEL;
    float acc[NE];
#pragma unroll
    for (int e = 0; e < NE; e++) acc[e] = 0.f;
    for (int d = lane; d < DMODEL; d += 32) {
        float xv = xr[d];
        const float* r = rw + d * NE;
#pragma unroll
        for (int e = 0; e < NE; e++) acc[e] = fmaf(xv, r[e], acc[e]);
    }
#pragma unroll
    for (int off = 16; off > 0; off >>= 1)
#pragma unroll
        for (int e = 0; e < NE; e++)
            acc[e] += __shfl_down_sync(0xffffffffu, acc[e], off);
    if (lane == 0) {
        float best = -1e30f, second = -1e30f;
        int b0 = 0, b1 = 0;
#pragma unroll
        for (int e = 0; e < NE; e++) {
            float l = acc[e] + rb[e];
            if (l > best)        { second = best; b1 = b0; best = l; b0 = e; }
            else if (l > second) { second = l; b1 = e; }
        }
        float w0 = 1.f / (1.f + __expf(second - best));
        g_tok_e[2*t+0] = b0;  g_tok_w[2*t+0] = w0;
        g_tok_e[2*t+1] = b1;  g_tok_w[2*t+1] = 1.f - w0;
        atomicAdd(&g_cnt[b0], 1);
        atomicAdd(&g_cnt[b1], 1);
    }
}

// ---------------- offsets ---------------------------------------------------
__global__ void offsets_kernel() {
    int o = 0;
    for (int e = 0; e < NE; e++) {
        g_pofs[e] = o;
        o += ((g_cnt[e] + BM - 1) / BM) * BM;
    }
    g_pofs[NE] = o;
}

// ---------------- scatter ---------------------------------------------------
__global__ void scatter_kernel() {
    int t = blockIdx.x * blockDim.x + threadIdx.x;
    if (t >= T_TOK) return;
#pragma unroll
    for (int k = 0; k < TOPK; k++) {
        int e = g_tok_e[2*t+k];
        int pos = g_pofs[e] + atomicAdd(&g_cur[e], 1);
        g_row_tok[pos] = t;
        g_tok_slot[2*t+k] = pos;
    }
}

// ---------------- grouped tf32 mma.sync GEMM --------------------------------
// Inputs pre-rounded to tf32 -> no cvt in inner loop.
// A fragments via ldmatrix.x4 (b16 trick, exact tf32 mapping); B scalar LDS.

#define A_STRIDE 36
#define B_STRIDE 136
#define A_BUF_BYTES (BM * A_STRIDE * 4)            // 18432
#define B_BUF_BYTES (BK * B_STRIDE * 4)            // 17408
#define SM_B_BASE   (3 * A_BUF_BYTES)              // 55296
#define SM_TOKS     (SM_B_BASE + 3 * B_BUF_BYTES)  // 107520
#define SMEM_TOTAL  (SM_TOKS + BM * 4)             // 108032

template<int KD, int NTOT, bool GATHER, bool RELU>
__global__ __launch_bounds__(256, 1)
void ffn_mma(const float* __restrict__ Asrc,
             const float* __restrict__ W,
             const float* __restrict__ bias,
             float* __restrict__ Out) {
    extern __shared__ __align__(128) char smem[];
    const int tid  = threadIdx.x;
    const int wid  = tid >> 5;
    const int lane = tid & 31;
    const int qid  = lane >> 2;   // 0..7
    const int rid  = lane & 3;    // 0..3
    const int wm   = wid >> 2;    // 0..1 (64 rows)
    const int wn   = wid & 3;     // 0..3 (32 cols)

    const int r0 = blockIdx.x * BM;
    if (r0 >= g_pofs[NE]) return;
    int e = 0;
    while (r0 >= g_pofs[e + 1]) e++;

    const uint32_t sb = smem_u32(smem);
    int* toks = (int*)(smem + SM_TOKS);
    if (GATHER) {
        if (tid < BM) toks[tid] = g_row_tok[r0 + tid];
        __syncthreads();
    }

    const float* We = W + (size_t)e * KD * NTOT;
    const int n0 = blockIdx.y * BN;

    // ldmatrix lane geometry for A: lane L -> matrix sel = L>>3, row-in-mat r = L&7
    //   matrix 0: rows +0..7,  cols k..k+3   -> a0
    //   matrix 1: rows +8..15, cols k..k+3   -> a1
    //   matrix 2: rows +0..7,  cols k+4..k+7 -> a2
    //   matrix 3: rows +8..15, cols k+4..k+7 -> a3
    const int sel = lane >> 3, lr = lane & 7;
    uint32_t a_lane_off[4];
#pragma unroll
    for (int mt = 0; mt < 4; mt++) {
        int arow = wm * 64 + mt * 16 + (sel & 1) * 8 + lr;
        int acol = (sel >> 1) * 4;
        a_lane_off[mt] = (uint32_t)((arow * A_STRIDE + acol) * 4);
    }

    // staging geometry
    const float* aptr[4];
    uint32_t     aoff[4];
    const float* bptr[4];
    uint32_t     boff[4];
#pragma unroll
    for (int t = 0; t < 4; t++) {
        int id  = tid + t * 256;
        int ar  = id >> 3, ac = id & 7;
        aptr[t] = (GATHER ? Asrc + (size_t)toks[ar] * KD
                          : Asrc + (size_t)(r0 + ar) * KD) + ac * 4;
        aoff[t] = (uint32_t)(ar * (A_STRIDE * 4) + ac * 16);
        int bk  = id >> 5, bc = id & 31;
        bptr[t] = We + (size_t)bk * NTOT + n0 + bc * 4;
        boff[t] = (uint32_t)(SM_B_BASE + bk * (B_STRIDE * 4) + bc * 16);
    }

    float acc[4][4][4];
#pragma unroll
    for (int i = 0; i < 4; i++)
#pragma unroll
        for (int j = 0; j < 4; j++)
#pragma unroll
            for (int k = 0; k < 4; k++) acc[i][j][k] = 0.f;

    const int NIT = KD / BK;

#pragma unroll
    for (int s = 0; s < 2; s++) {
#pragma unroll
        for (int t = 0; t < 4; t++) {
            cp16(sb + aoff[t] + s * A_BUF_BYTES, aptr[t] + s * BK);
            cp16(sb + boff[t] + s * B_BUF_BYTES, bptr[t] + (size_t)s * BK * NTOT);
        }
        CP_COMMIT();
    }

    for (int it = 0; it < NIT; it++) {
        int cur = it % 3;
        if (it + 2 < NIT) {
            int nxt = (it + 2) % 3;
            int k0 = (it + 2) * BK;
#pragma unroll
            for (int t = 0; t < 4; t++) {
                cp16(sb + aoff[t] + nxt * A_BUF_BYTES, aptr[t] + k0);
                cp16(sb + boff[t] + nxt * B_BUF_BYTES, bptr[t] + (size_t)k0 * NTOT);
            }
            CP_COMMIT();
            asm volatile("cp.async.wait_group 2;" ::: "memory");
        } else if (it + 1 < NIT) {
            asm volatile("cp.async.wait_group 1;" ::: "memory");
        } else {
            asm volatile("cp.async.wait_group 0;" ::: "memory");
        }
        __syncthreads();

        const uint32_t sbA = sb + cur * A_BUF_BYTES;
        const float* Bs = (const float*)(smem + SM_B_BASE + cur * B_BUF_BYTES);
#pragma unroll
        for (int ks = 0; ks < BK / 8; ks++) {
            const int kk = ks * 8;
            uint32_t a[4][4], b[4][2];
#pragma unroll
            for (int mt = 0; mt < 4; mt++)
                ldsm_x4(a[mt][0], a[mt][1], a[mt][2], a[mt][3],
                        sbA + a_lane_off[mt] + kk * 4);
#pragma unroll
            for (int nt = 0; nt < 4; nt++) {
                int col = wn * 32 + nt * 8 + qid;
                b[nt][0] = __float_as_uint(Bs[(kk + rid) * B_STRIDE + col]);
                b[nt][1] = __float_as_uint(Bs[(kk + rid + 4) * B_STRIDE + col]);
            }
#pragma unroll
            for (int mt = 0; mt < 4; mt++)
#pragma unroll
                for (int nt = 0; nt < 4; nt++)
                    mma_tf32(acc[mt][nt][0], acc[mt][nt][1], acc[mt][nt][2], acc[mt][nt][3],
                             a[mt][0], a[mt][1], a[mt][2], a[mt][3],
                             b[nt][0], b[nt][1]);
        }
        __syncthreads();
    }

    const float* be = bias + (size_t)e * NTOT + n0;
#pragma unroll
    for (int mt = 0; mt < 4; mt++) {
        int row = r0 + wm * 64 + mt * 16 + qid;
#pragma unroll
        for (int nt = 0; nt < 4; nt++) {
            int col = wn * 32 + nt * 8 + 2 * rid;
            float2 bv = *(const float2*)(be + col);
            float2 v0, v1;
            v0.x = acc[mt][nt][0] + bv.x;
            v0.y = acc[mt][nt][1] + bv.y;
            v1.x = acc[mt][nt][2] + bv.x;
            v1.y = acc[mt][nt][3] + bv.y;
            if (RELU) {
                // relu + tf32 pre-round for GEMM2's A operand
                v0.x = __uint_as_float(f2tf(fmaxf(v0.x, 0.f)));
                v0.y = __uint_as_float(f2tf(fmaxf(v0.y, 0.f)));
                v1.x = __uint_as_float(f2tf(fmaxf(v1.x, 0.f)));
                v1.y = __uint_as_float(f2tf(fmaxf(v1.y, 0.f)));
            }
            *(float2*)(Out + (size_t)row * NTOT + n0 + col)       = v0;
            *(float2*)(Out + (size_t)(row + 8) * NTOT + n0 + col) = v1;
        }
    }
}

// ---------------- combine ---------------------------------------------------
__global__ void combine_kernel(float* __restrict__ out) {
    int gid = blockIdx.x * blockDim.x + threadIdx.x;
    int t = gid >> 7;
    int j = (gid & 127) * 4;
    if (t >= T_TOK) return;
    int s0 = g_tok_slot[2*t], s1 = g_tok_slot[2*t+1];
    float w0 = g_tok_w[2*t], w1 = g_tok_w[2*t+1];
    float4 a = *(const float4*)(g_eout + (size_t)s0 * DMODEL + j);
    float4 b = *(const float4*)(g_eout + (size_t)s1 * DMODEL + j);
    float4 o;
    o.x = w0 * a.x + w1 * b.x;
    o.y = w0 * a.y + w1 * b.y;
    o.z = w0 * a.z + w1 * b.z;
    o.w = w0 * a.w + w1 * b.w;
    *(float4*)(out + (size_t)t * DMODEL + j) = o;
}

// ---------------------------------------------------------------------------
extern "C" void kernel_launch(void* const* d_in, const int* in_sizes, int n_in,
                              void* d_out, int out_size) {
    const float* x        = (const float*)d_in[0];
    const float* router_w = (const float*)d_in[1];
    const float* router_b = (const float*)d_in[2];
    const float* w1       = (const float*)d_in[3];
    const float* b1       = (const float*)d_in[4];
    const float* w2       = (const float*)d_in[5];
    const float* b2       = (const float*)d_in[6];
    float* out            = (float*)d_out;
    (void)in_sizes; (void)n_in; (void)out_size;

    float* hid; cudaGetSymbolAddress((void**)&hid, g_hidden);
    float* eo;  cudaGetSymbolAddress((void**)&eo,  g_eout);
    float* xr;  cudaGetSymbolAddress((void**)&xr,  g_xr);
    float* w1r; cudaGetSymbolAddress((void**)&w1r, g_w1r);
    float* w2r; cudaGetSymbolAddress((void**)&w2r, g_w2r);

    cudaFuncSetAttribute(ffn_mma<DMODEL, FF, true,  true >,
                         cudaFuncAttributeMaxDynamicSharedMemorySize, SMEM_TOTAL);
    cudaFuncSetAttribute(ffn_mma<FF, DMODEL, false, false>,
                         cudaFuncAttributeMaxDynamicSharedMemorySize, SMEM_TOTAL);

    init_kernel<<<(ROWS_MAX + 255) / 256, 256>>>();
    router_kernel<<<(T_TOK * 32 + 255) / 256, 256>>>(x, router_w, router_b);
    offsets_kernel<<<1, 1>>>();
    scatter_kernel<<<(T_TOK + 255) / 256, 256>>>();

    // tf32 pre-rounding (removes all cvt from GEMM inner loops)
    round_kernel<<<592, 256>>>(x,  xr,  T_TOK * DMODEL / 4);
    round_kernel<<<592, 256>>>(w1, w1r, NE * DMODEL * FF / 4);
    round_kernel<<<592, 256>>>(w2, w2r, NE * FF * DMODEL / 4);

    dim3 g1(ROWS_MAX / BM, FF / BN);       // 136 x 16
    ffn_mma<DMODEL, FF, true, true><<<g1, 256, SMEM_TOTAL>>>(xr, w1r, b1, hid);

    dim3 g2(ROWS_MAX / BM, DMODEL / BN);   // 136 x 4
    ffn_mma<FF, DMODEL, false, false><<<g2, 256, SMEM_TOTAL>>>(hid, w2r, b2, eo);

    combine_kernel<<<(T_TOK * 128 + 255) / 256, 256>>>(out);
}

// round 6
// speedup vs baseline: 3.4508x; 1.1315x over previous
#include <cuda_runtime.h>
#include <cstdint>
#include <math.h>

#define T_TOK   8192
#define DMODEL  512
#define FF      2048
#define NE      8
#define TOPK    2

#define BM 128
#define BN 256
#define BK 32
#define ROWS_MAX (TOPK*T_TOK + NE*BM)   // 17408

// ---------------- static device scratch -------------------------------------
__device__ float g_hidden[(size_t)ROWS_MAX * FF];     // tf32-rounded, k-contig
__device__ float g_eout[(size_t)ROWS_MAX * DMODEL];
__device__ float g_xr[(size_t)T_TOK * DMODEL];        // tf32-rounded x
__device__ float g_w1t[(size_t)NE * FF * DMODEL];     // [E][F][D] n-major k-contig, tf32
__device__ float g_w2t[(size_t)NE * DMODEL * FF];     // [E][D][F] n-major k-contig, tf32
__device__ int   g_row_tok[ROWS_MAX];
__device__ int   g_tok_e[T_TOK * TOPK];
__device__ int   g_tok_slot[T_TOK * TOPK];
__device__ float g_tok_w[T_TOK * TOPK];
__device__ int   g_cnt[NE];
__device__ int   g_cur[NE];
__device__ int   g_pofs[NE + 1];

// ---------------- helpers ---------------------------------------------------
__device__ __forceinline__ uint32_t smem_u32(const void* p) {
    uint32_t a;
    asm("{ .reg .u64 t; cvta.to.shared.u64 t, %1; cvt.u32.u64 %0, t; }" : "=r"(a) : "l"(p));
    return a;
}
__device__ __forceinline__ void cp16(uint32_t dst, const void* src) {
    asm volatile("cp.async.cg.shared.global [%0], [%1], 16;" :: "r"(dst), "l"(src));
}
#define CP_COMMIT() asm volatile("cp.async.commit_group;" ::: "memory")
__device__ __forceinline__ uint32_t f2tf(float f) {
    uint32_t u;
    asm("cvt.rna.tf32.f32 %0, %1;" : "=r"(u) : "f"(f));
    return u;
}
__device__ __forceinline__ void ldsm_x4(uint32_t& r0, uint32_t& r1, uint32_t& r2, uint32_t& r3,
                                        uint32_t addr) {
    asm volatile("ldmatrix.sync.aligned.m8n8.x4.shared.b16 {%0,%1,%2,%3}, [%4];"
                 : "=r"(r0), "=r"(r1), "=r"(r2), "=r"(r3) : "r"(addr));
}
__device__ __forceinline__ void mma_tf32(float& c0, float& c1, float& c2, float& c3,
                                         uint32_t a0, uint32_t a1, uint32_t a2, uint32_t a3,
                                         uint32_t b0, uint32_t b1) {
    asm volatile(
        "mma.sync.aligned.m16n8k8.row.col.f32.tf32.tf32.f32 "
        "{%0,%1,%2,%3}, {%4,%5,%6,%7}, {%8,%9}, {%0,%1,%2,%3};"
        : "+f"(c0), "+f"(c1), "+f"(c2), "+f"(c3)
        : "r"(a0), "r"(a1), "r"(a2), "r"(a3), "r"(b0), "r"(b1));
}

// ---------------- init ------------------------------------------------------
__global__ void init_kernel() {
    int i = blockIdx.x * blockDim.x + threadIdx.x;
    if (i < NE) { g_cnt[i] = 0; g_cur[i] = 0; }
    if (i < ROWS_MAX) g_row_tok[i] = 0;
}

// ---------------- elementwise tf32 rounding (for x) -------------------------
__global__ void round_kernel(const float* __restrict__ src, float* __restrict__ dst, int n4) {
    int i = blockIdx.x * blockDim.x + threadIdx.x;
    int stride = gridDim.x * blockDim.x;
    for (; i < n4; i += stride) {
        float4 v = ((const float4*)src)[i];
        v.x = __uint_as_float(f2tf(v.x));
        v.y = __uint_as_float(f2tf(v.y));
        v.z = __uint_as_float(f2tf(v.z));
        v.w = __uint_as_float(f2tf(v.w));
        ((float4*)dst)[i] = v;
    }
}

// ---------------- transpose + tf32 round: [E][R][C] -> [E][C][R] ------------
__global__ void transpose_round_kernel(const float* __restrict__ src, float* __restrict__ dst,
                                       int R, int C) {
    __shared__ float tile[32][33];
    int e = blockIdx.z;
    int c0 = blockIdx.x * 32, r0 = blockIdx.y * 32;
    const float* s = src + (size_t)e * R * C;
    float* d = dst + (size_t)e * R * C;
#pragma unroll
    for (int i = 0; i < 32; i += 8)
        tile[threadIdx.y + i][threadIdx.x] =
            s[(size_t)(r0 + threadIdx.y + i) * C + c0 + threadIdx.x];
    __syncthreads();
#pragma unroll
    for (int i = 0; i < 32; i += 8)
        d[(size_t)(c0 + threadIdx.y + i) * R + r0 + threadIdx.x] =
            __uint_as_float(f2tf(tile[threadIdx.x][threadIdx.y + i]));
}

// ---------------- router ----------------------------------------------------
__global__ void router_kernel(const float* __restrict__ x,
                              const float* __restrict__ rw,
                              const float* __restrict__ rb) {
    int gtid = blockIdx.x * blockDim.x + threadIdx.x;
    int t = gtid >> 5, lane = gtid & 31;
    if (t >= T_TOK) return;
    const float* xr = x + (size_t)t * DMODEL;
    float acc[NE];
#pragma unroll
    for (int e = 0; e < NE; e++) acc[e] = 0.f;
    for (int d = lane; d < DMODEL; d += 32) {
        float xv = xr[d];
        const float* r = rw + d * NE;
#pragma unroll
        for (int e = 0; e < NE; e++) acc[e] = fmaf(xv, r[e], acc[e]);
    }
#pragma unroll
    for (int off = 16; off > 0; off >>= 1)
#pragma unroll
        for (int e = 0; e < NE; e++)
            acc[e] += __shfl_down_sync(0xffffffffu, acc[e], off);
    if (lane == 0) {
        float best = -1e30f, second = -1e30f;
        int b0 = 0, b1 = 0;
#pragma unroll
        for (int e = 0; e < NE; e++) {
            float l = acc[e] + rb[e];
            if (l > best)        { second = best; b1 = b0; best = l; b0 = e; }
            else if (l > second) { second = l; b1 = e; }
        }
        float w0 = 1.f / (1.f + __expf(second - best));
        g_tok_e[2*t+0] = b0;  g_tok_w[2*t+0] = w0;
        g_tok_e[2*t+1] = b1;  g_tok_w[2*t+1] = 1.f - w0;
        atomicAdd(&g_cnt[b0], 1);
        atomicAdd(&g_cnt[b1], 1);
    }
}

// ---------------- offsets ---------------------------------------------------
__global__ void offsets_kernel() {
    int o = 0;
    for (int e = 0; e < NE; e++) {
        g_pofs[e] = o;
        o += ((g_cnt[e] + BM - 1) / BM) * BM;
    }
    g_pofs[NE] = o;
}

// ---------------- scatter ---------------------------------------------------
__global__ void scatter_kernel() {
    int t = blockIdx.x * blockDim.x + threadIdx.x;
    if (t >= T_TOK) return;
#pragma unroll
    for (int k = 0; k < TOPK; k++) {
        int e = g_tok_e[2*t+k];
        int pos = g_pofs[e] + atomicAdd(&g_cur[e], 1);
        g_row_tok[pos] = t;
        g_tok_slot[2*t+k] = pos;
    }
}

// ---------------- grouped tf32 mma.sync GEMM --------------------------------
// C[128x256] = A[128 x KD] @ W_e^T  (W stored n-major rows, k-contiguous)
// 8 warps, 64x64 warp tiles (2m x 4n); all fragments via ldmatrix.x4.b16.

#define ROW_BYTES 144                              // 32 k floats + 16B pad
#define A_BUF_BYTES (BM * ROW_BYTES)               // 18432
#define B_BUF_BYTES (BN * ROW_BYTES)               // 36864
#define SM_B_BASE   (3 * A_BUF_BYTES)              // 55296
#define SM_TOKS     (SM_B_BASE + 3 * B_BUF_BYTES)  // 165888
#define SMEM_TOTAL  (SM_TOKS + BM * 4)             // 166400

template<int KD, int NTOT, bool GATHER, bool RELU>
__global__ __launch_bounds__(256, 1)
void ffn_mma(const float* __restrict__ Asrc,
             const float* __restrict__ Wt,     // [E][NTOT][KD]
             const float* __restrict__ bias,
             float* __restrict__ Out) {
    extern __shared__ __align__(128) char smem[];
    const int tid  = threadIdx.x;
    const int wid  = tid >> 5;
    const int lane = tid & 31;
    const int qid  = lane >> 2;
    const int rid  = lane & 3;
    const int wm   = wid >> 2;    // 0..1 (64 rows)
    const int wn   = wid & 3;     // 0..3 (64 cols)

    const int r0 = blockIdx.x * BM;
    if (r0 >= g_pofs[NE]) return;
    int e = 0;
    while (r0 >= g_pofs[e + 1]) e++;

    const uint32_t sb = smem_u32(smem);
    int* toks = (int*)(smem + SM_TOKS);
    if (GATHER) {
        if (tid < BM) toks[tid] = g_row_tok[r0 + tid];
        __syncthreads();
    }

    const float* We = Wt + (size_t)e * (size_t)NTOT * KD;
    const int n0 = blockIdx.y * BN;

    // ldmatrix lane base offsets (within a stage buffer, before +kk*4)
    const int sel = lane >> 3, lr = lane & 7;
    uint32_t a_lane_off[4];
#pragma unroll
    for (int mt = 0; mt < 4; mt++) {
        int arow = wm * 64 + mt * 16 + (sel & 1) * 8 + lr;
        int acol = (sel >> 1) * 4;                     // k sub-offset
        a_lane_off[mt] = (uint32_t)(arow * ROW_BYTES + acol * 4);
    }
    uint32_t b_lane_off[4];                            // nt pairs (0,1),(2,3),(4,5),(6,7)
#pragma unroll
    for (int g = 0; g < 4; g++) {
        int brow = wn * 64 + (2 * g + (sel >> 1)) * 8 + lr;
        int bcol = (sel & 1) * 4;
        b_lane_off[g] = (uint32_t)(SM_B_BASE + brow * ROW_BYTES + bcol * 4);
    }

    // staging geometry: A 4 chunks/thread, B 8 chunks/thread (16B each)
    const float* aptr[4];
    uint32_t     aoff[4];
#pragma unroll
    for (int t = 0; t < 4; t++) {
        int id = tid + t * 256;
        int ar = id >> 3, kc = id & 7;
        aptr[t] = (GATHER ? Asrc + (size_t)toks[ar] * KD
                          : Asrc + (size_t)(r0 + ar) * KD) + kc * 4;
        aoff[t] = (uint32_t)(ar * ROW_BYTES + kc * 16);
    }
    const float* bptr[8];
    uint32_t     boff[8];
#pragma unroll
    for (int t = 0; t < 8; t++) {
        int id = tid + t * 256;
        int br = id >> 3, kc = id & 7;
        bptr[t] = We + (size_t)(n0 + br) * KD + kc * 4;
        boff[t] = (uint32_t)(SM_B_BASE + br * ROW_BYTES + kc * 16);
    }

    float acc[4][8][4];
#pragma unroll
    for (int i = 0; i < 4; i++)
#pragma unroll
        for (int j = 0; j < 8; j++)
#pragma unroll
            for (int k = 0; k < 4; k++) acc[i][j][k] = 0.f;

    const int NIT = KD / BK;

#pragma unroll
    for (int s = 0; s < 2; s++) {
#pragma unroll
        for (int t = 0; t < 4; t++)
            cp16(sb + aoff[t] + s * A_BUF_BYTES, aptr[t] + s * BK);
#pragma unroll
        for (int t = 0; t < 8; t++)
            cp16(sb + boff[t] + s * B_BUF_BYTES, bptr[t] + s * BK);
        CP_COMMIT();
    }

    for (int it = 0; it < NIT; it++) {
        int cur = it % 3;
        if (it + 2 < NIT) {
            int nxt = (it + 2) % 3;
            int k0 = (it + 2) * BK;
#pragma unroll
            for (int t = 0; t < 4; t++)
                cp16(sb + aoff[t] + nxt * A_BUF_BYTES, aptr[t] + k0);
#pragma unroll
            for (int t = 0; t < 8; t++)
                cp16(sb + boff[t] + nxt * B_BUF_BYTES, bptr[t] + k0);
            CP_COMMIT();
            asm volatile("cp.async.wait_group 2;" ::: "memory");
        } else if (it + 1 < NIT) {
            asm volatile("cp.async.wait_group 1;" ::: "memory");
        } else {
            asm volatile("cp.async.wait_group 0;" ::: "memory");
        }
        __syncthreads();

        const uint32_t sbA = sb + cur * A_BUF_BYTES;
        const uint32_t sbB = sb + cur * B_BUF_BYTES;
#pragma unroll
        for (int ks = 0; ks < BK / 8; ks++) {
            const uint32_t kb = ks * 32;   // 8 k floats = 32 bytes
            uint32_t a[4][4], b[8][2];
#pragma unroll
            for (int mt = 0; mt < 4; mt++)
                ldsm_x4(a[mt][0], a[mt][1], a[mt][2], a[mt][3],
                        sbA + a_lane_off[mt] + kb);
#pragma unroll
            for (int g = 0; g < 4; g++)
                ldsm_x4(b[2*g][0], b[2*g][1], b[2*g+1][0], b[2*g+1][1],
                        sbB + b_lane_off[g] + kb);
#pragma unroll
            for (int mt = 0; mt < 4; mt++)
#pragma unroll
                for (int nt = 0; nt < 8; nt++)
                    mma_tf32(acc[mt][nt][0], acc[mt][nt][1], acc[mt][nt][2], acc[mt][nt][3],
                             a[mt][0], a[mt][1], a[mt][2], a[mt][3],
                             b[nt][0], b[nt][1]);
        }
        __syncthreads();
    }

    const float* be = bias + (size_t)e * NTOT + n0;
#pragma unroll
    for (int mt = 0; mt < 4; mt++) {
        int row = r0 + wm * 64 + mt * 16 + qid;
#pragma unroll
        for (int nt = 0; nt < 8; nt++) {
            int col = wn * 64 + nt * 8 + 2 * rid;
            float2 bv = *(const float2*)(be + col);
            float2 v0, v1;
            v0.x = acc[mt][nt][0] + bv.x;
            v0.y = acc[mt][nt][1] + bv.y;
            v1.x = acc[mt][nt][2] + bv.x;
            v1.y = acc[mt][nt][3] + bv.y;
            if (RELU) {
                v0.x = __uint_as_float(f2tf(fmaxf(v0.x, 0.f)));
                v0.y = __uint_as_float(f2tf(fmaxf(v0.y, 0.f)));
                v1.x = __uint_as_float(f2tf(fmaxf(v1.x, 0.f)));
                v1.y = __uint_as_float(f2tf(fmaxf(v1.y, 0.f)));
            }
            *(float2*)(Out + (size_t)row * NTOT + n0 + col)       = v0;
            *(float2*)(Out + (size_t)(row + 8) * NTOT + n0 + col) = v1;
        }
    }
}

// ---------------- combine ---------------------------------------------------
__global__ void combine_kernel(float* __restrict__ out) {
    int gid = blockIdx.x * blockDim.x + threadIdx.x;
    int t = gid >> 7;
    int j = (gid & 127) * 4;
    if (t >= T_TOK) return;
    int s0 = g_tok_slot[2*t], s1 = g_tok_slot[2*t+1];
    float w0 = g_tok_w[2*t], w1 = g_tok_w[2*t+1];
    float4 a = *(const float4*)(g_eout + (size_t)s0 * DMODEL + j);
    float4 b = *(const float4*)(g_eout + (size_t)s1 * DMODEL + j);
    float4 o;
    o.x = w0 * a.x + w1 * b.x;
    o.y = w0 * a.y + w1 * b.y;
    o.z = w0 * a.z + w1 * b.z;
    o.w = w0 * a.w + w1 * b.w;
    *(float4*)(out + (size_t)t * DMODEL + j) = o;
}

// ---------------------------------------------------------------------------
extern "C" void kernel_launch(void* const* d_in, const int* in_sizes, int n_in,
                              void* d_out, int out_size) {
    const float* x        = (const float*)d_in[0];
    const float* router_w = (const float*)d_in[1];
    const float* router_b = (const float*)d_in[2];
    const float* w1       = (const float*)d_in[3];
    const float* b1       = (const float*)d_in[4];
    const float* w2       = (const float*)d_in[5];
    const float* b2       = (const float*)d_in[6];
    float* out            = (float*)d_out;
    (void)in_sizes; (void)n_in; (void)out_size;

    float* hid; cudaGetSymbolAddress((void**)&hid, g_hidden);
    float* eo;  cudaGetSymbolAddress((void**)&eo,  g_eout);
    float* xr;  cudaGetSymbolAddress((void**)&xr,  g_xr);
    float* w1t; cudaGetSymbolAddress((void**)&w1t, g_w1t);
    float* w2t; cudaGetSymbolAddress((void**)&w2t, g_w2t);

    cudaFuncSetAttribute(ffn_mma<DMODEL, FF, true,  true >,
                         cudaFuncAttributeMaxDynamicSharedMemorySize, SMEM_TOTAL);
    cudaFuncSetAttribute(ffn_mma<FF, DMODEL, false, false>,
                         cudaFuncAttributeMaxDynamicSharedMemorySize, SMEM_TOTAL);

    init_kernel<<<(ROWS_MAX + 255) / 256, 256>>>();
    router_kernel<<<(T_TOK * 32 + 255) / 256, 256>>>(x, router_w, router_b);
    offsets_kernel<<<1, 1>>>();
    scatter_kernel<<<(T_TOK + 255) / 256, 256>>>();

    round_kernel<<<592, 256>>>(x, xr, T_TOK * DMODEL / 4);
    // w1 [E][D][F] -> w1t [E][F][D] (rounded);  w2 [E][F][D] -> w2t [E][D][F]
    transpose_round_kernel<<<dim3(FF/32, DMODEL/32, NE), dim3(32, 8)>>>(w1, w1t, DMODEL, FF);
    transpose_round_kernel<<<dim3(DMODEL/32, FF/32, NE), dim3(32, 8)>>>(w2, w2t, FF, DMODEL);

    dim3 g1(ROWS_MAX / BM, FF / BN);       // 136 x 8
    ffn_mma<DMODEL, FF, true, true><<<g1, 256, SMEM_TOTAL>>>(xr, w1t, b1, hid);

    dim3 g2(ROWS_MAX / BM, DMODEL / BN);   // 136 x 2
    ffn_mma<FF, DMODEL, false, false><<<g2, 256, SMEM_TOTAL>>>(hid, w2t, b2, eo);

    combine_kernel<<<(T_TOK * 128 + 255) / 256, 256>>>(out);
}

// round 7
// speedup vs baseline: 4.2402x; 1.2287x over previous
#include <cuda_runtime.h>
#include <cstdint>
#include <math.h>

#define T_TOK   8192
#define DMODEL  512
#define FF      2048
#define NE      8
#define TOPK    2

#define BM 128
#define BN 256
#define BK 32
#define ROWS_MAX (TOPK*T_TOK + NE*BM)   // 17408
#define RTILES   (ROWS_MAX / BM)        // 136

// ---------------- static device scratch -------------------------------------
// tiled layouts: [tile][kchunk][block of rows*32 floats, swizzled]
__device__ float g_hidden[(size_t)ROWS_MAX * FF];     // [136][64][4096]
__device__ float g_eout[(size_t)ROWS_MAX * DMODEL];   // row-major
__device__ float g_xg[(size_t)ROWS_MAX * DMODEL];     // [136][16][4096] gathered+rounded
__device__ float g_w1t[(size_t)NE * FF * DMODEL];     // [8][8][16][8192]
__device__ float g_w2t[(size_t)NE * DMODEL * FF];     // [8][2][64][8192]
__device__ int   g_row_tok[ROWS_MAX];
__device__ int   g_tok_e[T_TOK * TOPK];
__device__ int   g_tok_slot[T_TOK * TOPK];
__device__ float g_tok_w[T_TOK * TOPK];
__device__ int   g_cnt[NE];
__device__ int   g_cur[NE];
__device__ int   g_pofs[NE + 1];

// ---------------- helpers ---------------------------------------------------
__device__ __forceinline__ uint32_t smem_u32(const void* p) {
    uint32_t a;
    asm("{ .reg .u64 t; cvta.to.shared.u64 t, %1; cvt.u32.u64 %0, t; }" : "=r"(a) : "l"(p));
    return a;
}
__device__ __forceinline__ uint32_t f2tf(float f) {
    uint32_t u;
    asm("cvt.rna.tf32.f32 %0, %1;" : "=r"(u) : "f"(f));
    return u;
}
__device__ __forceinline__ void ldsm_x4(uint32_t& r0, uint32_t& r1, uint32_t& r2, uint32_t& r3,
                                        uint32_t addr) {
    asm volatile("ldmatrix.sync.aligned.m8n8.x4.shared.b16 {%0,%1,%2,%3}, [%4];"
                 : "=r"(r0), "=r"(r1), "=r"(r2), "=r"(r3) : "r"(addr));
}
__device__ __forceinline__ void mma_tf32(float& c0, float& c1, float& c2, float& c3,
                                         uint32_t a0, uint32_t a1, uint32_t a2, uint32_t a3,
                                         uint32_t b0, uint32_t b1) {
    asm volatile(
        "mma.sync.aligned.m16n8k8.row.col.f32.tf32.tf32.f32 "
        "{%0,%1,%2,%3}, {%4,%5,%6,%7}, {%8,%9}, {%0,%1,%2,%3};"
        : "+f"(c0), "+f"(c1), "+f"(c2), "+f"(c3)
        : "r"(a0), "r"(a1), "r"(a2), "r"(a3), "r"(b0), "r"(b1));
}
#define MBARRIER_INIT(addr, cnt) \
    asm volatile("mbarrier.init.shared.b64 [%0], %1;" :: "r"(addr), "r"(cnt) : "memory")
__device__ __forceinline__ void mbar_expect(uint32_t mbar, uint32_t bytes) {
    asm volatile("mbarrier.arrive.expect_tx.shared.b64 _, [%0], %1;"
                 :: "r"(mbar), "r"(bytes) : "memory");
}
__device__ __forceinline__ void bulk_g2s(uint32_t dst, const void* src, uint32_t bytes,
                                         uint32_t mbar) {
    asm volatile("cp.async.bulk.shared::cta.global.mbarrier::complete_tx::bytes "
                 "[%0], [%1], %2, [%3];"
                 :: "r"(dst), "l"(src), "r"(bytes), "r"(mbar) : "memory");
}
__device__ __forceinline__ void mbar_wait(uint32_t mbar, uint32_t parity) {
    uint32_t done;
    asm volatile(
        "{ .reg .pred p; mbarrier.try_wait.parity.acquire.cta.shared::cta.b64 p, [%1], %2; selp.b32 %0, 1, 0, p; }"
        : "=r"(done) : "r"(mbar), "r"(parity) : "memory");
    if (!done) {
        asm volatile(
            "{ .reg .pred P1;\n"
            "WAIT_LOOP_%=:\n"
            "mbarrier.try_wait.parity.acquire.cta.shared::cta.b64 P1, [%0], %1, 0x989680;\n"
            "@P1 bra.uni WAIT_DONE_%=;\n"
            "bra.uni WAIT_LOOP_%=;\n"
            "WAIT_DONE_%=:\n}"
            :: "r"(mbar), "r"(parity) : "memory");
    }
}

// ---------------- init ------------------------------------------------------
__global__ void init_kernel() {
    int i = blockIdx.x * blockDim.x + threadIdx.x;
    if (i < NE) { g_cnt[i] = 0; g_cur[i] = 0; }
    if (i < ROWS_MAX) g_row_tok[i] = 0;
}

// ---------------- router ----------------------------------------------------
__global__ void router_kernel(const float* __restrict__ x,
                              const float* __restrict__ rw,
                              const float* __restrict__ rb) {
    int gtid = blockIdx.x * blockDim.x + threadIdx.x;
    int t = gtid >> 5, lane = gtid & 31;
    if (t >= T_TOK) return;
    const float* xr = x + (size_t)t * DMODEL;
    float acc[NE];
#pragma unroll
    for (int e = 0; e < NE; e++) acc[e] = 0.f;
    for (int d = lane; d < DMODEL; d += 32) {
        float xv = xr[d];
        const float* r = rw + d * NE;
#pragma unroll
        for (int e = 0; e < NE; e++) acc[e] = fmaf(xv, r[e], acc[e]);
    }
#pragma unroll
    for (int off = 16; off > 0; off >>= 1)
#pragma unroll
        for (int e = 0; e < NE; e++)
            acc[e] += __shfl_down_sync(0xffffffffu, acc[e], off);
    if (lane == 0) {
        float best = -1e30f, second = -1e30f;
        int b0 = 0, b1 = 0;
#pragma unroll
        for (int e = 0; e < NE; e++) {
            float l = acc[e] + rb[e];
            if (l > best)        { second = best; b1 = b0; best = l; b0 = e; }
            else if (l > second) { second = l; b1 = e; }
        }
        float w0 = 1.f / (1.f + __expf(second - best));
        g_tok_e[2*t+0] = b0;  g_tok_w[2*t+0] = w0;
        g_tok_e[2*t+1] = b1;  g_tok_w[2*t+1] = 1.f - w0;
        atomicAdd(&g_cnt[b0], 1);
        atomicAdd(&g_cnt[b1], 1);
    }
}

// ---------------- offsets ---------------------------------------------------
__global__ void offsets_kernel() {
    int o = 0;
    for (int e = 0; e < NE; e++) {
        g_pofs[e] = o;
        o += ((g_cnt[e] + BM - 1) / BM) * BM;
    }
    g_pofs[NE] = o;
}

// ---------------- scatter ---------------------------------------------------
__global__ void scatter_kernel() {
    int t = blockIdx.x * blockDim.x + threadIdx.x;
    if (t >= T_TOK) return;
#pragma unroll
    for (int k = 0; k < TOPK; k++) {
        int e = g_tok_e[2*t+k];
        int pos = g_pofs[e] + atomicAdd(&g_cur[e], 1);
        g_row_tok[pos] = t;
        g_tok_slot[2*t+k] = pos;
    }
}

// ---------------- gather x into tiled-swizzled slot layout ------------------
// g_xg[rtile][kch][4096]: elem (r=slot%128, k) at r*32 + ((k>>2 & 7) ^ (r&7))*4 + (k&3)
__global__ void gather_round_kernel(const float* __restrict__ x) {
    int id = blockIdx.x * blockDim.x + threadIdx.x;   // one 16B unit each
    const int UNITS = DMODEL / 4;                      // 128
    if (id >= ROWS_MAX * UNITS) return;
    int s  = id / UNITS;
    int kq = id % UNITS;            // 16B unit index within the row
    int kch = kq >> 3;              // k chunk (32 floats)
    int u   = kq & 7;               // unit within chunk
    int r   = s & (BM - 1);
    int tok = g_row_tok[s];
    float4 v = *(const float4*)(x + (size_t)tok * DMODEL + kq * 4);
    v.x = __uint_as_float(f2tf(v.x));
    v.y = __uint_as_float(f2tf(v.y));
    v.z = __uint_as_float(f2tf(v.z));
    v.w = __uint_as_float(f2tf(v.w));
    size_t base = ((size_t)(s >> 7) * (DMODEL / 32) + kch) * 4096;
    *(float4*)(g_xg + base + r * 32 + ((u ^ (r & 7)) << 2)) = v;
}

// ---------------- weight transpose+round into tiled-swizzled layout ---------
// src [E][R][C] (R=k, C=n) -> dst [E][C/256][R/32][8192]
// elem (n,k): block (n>>8, k>>5); in-block (n&255)*32 + (((k&31)>>2)^((n&255)&7))*4 + (k&3)
__global__ void transpose_round_kernel(const float* __restrict__ src, float* __restrict__ dst,
                                       int R, int C) {
    __shared__ float tile[32][33];
    int e = blockIdx.z;
    int c0 = blockIdx.x * 32, r0 = blockIdx.y * 32;   // c=n, r=k
    const float* s = src + (size_t)e * R * C;
#pragma unroll
    for (int i = 0; i < 32; i += 8)
        tile[threadIdx.y + i][threadIdx.x] =
            s[(size_t)(r0 + threadIdx.y + i) * C + c0 + threadIdx.x];
    __syncthreads();
    // thread: n_local = tx, k group = ty (4 consecutive k)
    int n = c0 + threadIdx.x;
    int k4 = threadIdx.y;                              // 0..7
    float4 v;
    v.x = __uint_as_float(f2tf(tile[k4 * 4 + 0][threadIdx.x]));
    v.y = __uint_as_float(f2tf(tile[k4 * 4 + 1][threadIdx.x]));
    v.z = __uint_as_float(f2tf(tile[k4 * 4 + 2][threadIdx.x]));
    v.w = __uint_as_float(f2tf(tile[k4 * 4 + 3][threadIdx.x]));
    int nn = n & 255;
    size_t base = (((size_t)e * (C >> 8) + (n >> 8)) * (R >> 5) + blockIdx.y) * 8192;
    *(float4*)(dst + base + nn * 32 + (((k4) ^ (nn & 7)) << 2)) = v;
}

// ---------------- grouped tf32 mma.sync GEMM, bulk-copy pipeline ------------
// A: tiled [rtile][KD/32][4096], B: tiled [E-sub][ntile][KD/32][8192], swizzled.
#define A_STAGE 16384
#define B_STAGE 32768
#define STAGE_BYTES (A_STAGE + B_STAGE)            // 49152
#define SM_MB (3 * STAGE_BYTES)                    // 147456
#define SMEM_TOTAL (SM_MB + 64)

template<int KD, int NTOT, bool TILED_OUT>
__global__ __launch_bounds__(256, 1)
void ffn_mma(const float* __restrict__ Atiled,
             const float* __restrict__ Wt,
             const float* __restrict__ bias,
             float* __restrict__ Out) {
    extern __shared__ __align__(128) char smem[];
    const int tid  = threadIdx.x;
    const int wid  = tid >> 5;
    const int lane = tid & 31;
    const int qid  = lane >> 2;
    const int rid  = lane & 3;
    const int wm   = wid >> 2;
    const int wn   = wid & 3;

    const int r0 = blockIdx.x * BM;
    if (r0 >= g_pofs[NE]) return;
    int e = 0;
    while (r0 >= g_pofs[e + 1]) e++;

    const uint32_t sb = smem_u32(smem);
    if (tid == 0) {
        MBARRIER_INIT(sb + SM_MB,      1);
        MBARRIER_INIT(sb + SM_MB + 8,  1);
        MBARRIER_INIT(sb + SM_MB + 16, 1);
    }
    __syncthreads();

    const int NCH = KD / 32;
    const float* Asrc = Atiled + (size_t)blockIdx.x * NCH * 4096;
    const float* Bsrc = Wt + (((size_t)e * (NTOT / 256) + blockIdx.y) * NCH) * 8192;
    const int n0 = blockIdx.y * BN;

    // ldmatrix lane geometry (swizzled): addr = row*128 + ((u ^ (row&7))<<4)
    const int sel = lane >> 3, lr = lane & 7;
    uint32_t a_base[4], a_s7[4];
#pragma unroll
    for (int mt = 0; mt < 4; mt++) {
        int arow = wm * 64 + mt * 16 + (sel & 1) * 8 + lr;
        a_base[mt] = (uint32_t)(arow * 128);
        a_s7[mt]   = (uint32_t)(arow & 7);
    }
    const uint32_t ua0 = (uint32_t)(sel >> 1);        // A k-unit base (0/1)
    uint32_t b_base[4], b_s7[4];
#pragma unroll
    for (int g = 0; g < 4; g++) {
        int brow = wn * 64 + (2 * g + (sel >> 1)) * 8 + lr;
        b_base[g] = (uint32_t)(A_STAGE + brow * 128);
        b_s7[g]   = (uint32_t)(brow & 7);
    }
    const uint32_t ub0 = (uint32_t)(sel & 1);

    float acc[4][8][4];
#pragma unroll
    for (int i = 0; i < 4; i++)
#pragma unroll
        for (int j = 0; j < 8; j++)
#pragma unroll
            for (int k = 0; k < 4; k++) acc[i][j][k] = 0.f;

    const int NIT = NCH;

    if (tid == 0) {
#pragma unroll
        for (int s = 0; s < 2; s++) {
            mbar_expect(sb + SM_MB + 8 * s, STAGE_BYTES);
            bulk_g2s(sb + s * STAGE_BYTES,           Asrc + (size_t)s * 4096, A_STAGE,
                     sb + SM_MB + 8 * s);
            bulk_g2s(sb + s * STAGE_BYTES + A_STAGE, Bsrc + (size_t)s * 8192, B_STAGE,
                     sb + SM_MB + 8 * s);
        }
    }

    for (int it = 0; it < NIT; it++) {
        int stage = it % 3;
        if (it + 2 < NIT && tid == 0) {
            int s2 = (it + 2) % 3;
            mbar_expect(sb + SM_MB + 8 * s2, STAGE_BYTES);
            bulk_g2s(sb + s2 * STAGE_BYTES,           Asrc + (size_t)(it + 2) * 4096, A_STAGE,
                     sb + SM_MB + 8 * s2);
            bulk_g2s(sb + s2 * STAGE_BYTES + A_STAGE, Bsrc + (size_t)(it + 2) * 8192, B_STAGE,
                     sb + SM_MB + 8 * s2);
        }
        mbar_wait(sb + SM_MB + 8 * stage, (it / 3) & 1);

        const uint32_t sbS = sb + stage * STAGE_BYTES;
#pragma unroll
        for (int ks = 0; ks < 4; ks++) {
            uint32_t a[4][4], b[8][2];
#pragma unroll
            for (int mt = 0; mt < 4; mt++)
                ldsm_x4(a[mt][0], a[mt][1], a[mt][2], a[mt][3],
                        sbS + a_base[mt] + (((ua0 + 2 * ks) ^ a_s7[mt]) << 4));
#pragma unroll
            for (int g = 0; g < 4; g++)
                ldsm_x4(b[2*g][0], b[2*g][1], b[2*g+1][0], b[2*g+1][1],
                        sbS + b_base[g] + (((ub0 + 2 * ks) ^ b_s7[g]) << 4));
#pragma unroll
            for (int mt = 0; mt < 4; mt++)
#pragma unroll
                for (int nt = 0; nt < 8; nt++)
                    mma_tf32(acc[mt][nt][0], acc[mt][nt][1], acc[mt][nt][2], acc[mt][nt][3],
                             a[mt][0], a[mt][1], a[mt][2], a[mt][3],
                             b[nt][0], b[nt][1]);
        }
        __syncthreads();
    }

    const float* be = bias + (size_t)e * NTOT + n0;
#pragma unroll
    for (int mt = 0; mt < 4; mt++) {
        int rowl = wm * 64 + mt * 16 + qid;           // local row
#pragma unroll
        for (int nt = 0; nt < 8; nt++) {
            int col = wn * 64 + nt * 8 + 2 * rid;     // local col (0..255)
            float2 bv = *(const float2*)(be + col);
            float2 v0, v1;
            v0.x = acc[mt][nt][0] + bv.x;
            v0.y = acc[mt][nt][1] + bv.y;
            v1.x = acc[mt][nt][2] + bv.x;
            v1.y = acc[mt][nt][3] + bv.y;
            if (TILED_OUT) {
                // relu + round + tiled-swizzled store into hidden
                v0.x = __uint_as_float(f2tf(fmaxf(v0.x, 0.f)));
                v0.y = __uint_as_float(f2tf(fmaxf(v0.y, 0.f)));
                v1.x = __uint_as_float(f2tf(fmaxf(v1.x, 0.f)));
                v1.y = __uint_as_float(f2tf(fmaxf(v1.y, 0.f)));
                int n = n0 + col;
                size_t base = ((size_t)blockIdx.x * (NTOT >> 5) + (n >> 5)) * 4096;
                int u = (n & 31) >> 2, lo = n & 3;
                int r0l = rowl, r1l = rowl + 8;
                *(float2*)(Out + base + r0l * 32 + ((u ^ (r0l & 7)) << 2) + lo) = v0;
                *(float2*)(Out + base + r1l * 32 + ((u ^ (r1l & 7)) << 2) + lo) = v1;
            } else {
                int row = r0 + rowl;
                *(float2*)(Out + (size_t)row * NTOT + n0 + col)       = v0;
                *(float2*)(Out + (size_t)(row + 8) * NTOT + n0 + col) = v1;
            }
        }
    }
}

// ---------------- combine ---------------------------------------------------
__global__ void combine_kernel(float* __restrict__ out) {
    int gid = blockIdx.x * blockDim.x + threadIdx.x;
    int t = gid >> 7;
    int j = (gid & 127) * 4;
    if (t >= T_TOK) return;
    int s0 = g_tok_slot[2*t], s1 = g_tok_slot[2*t+1];
    float w0 = g_tok_w[2*t], w1 = g_tok_w[2*t+1];
    float4 a = *(const float4*)(g_eout + (size_t)s0 * DMODEL + j);
    float4 b = *(const float4*)(g_eout + (size_t)s1 * DMODEL + j);
    float4 o;
    o.x = w0 * a.x + w1 * b.x;
    o.y = w0 * a.y + w1 * b.y;
    o.z = w0 * a.z + w1 * b.z;
    o.w = w0 * a.w + w1 * b.w;
    *(float4*)(out + (size_t)t * DMODEL + j) = o;
}

// ---------------------------------------------------------------------------
extern "C" void kernel_launch(void* const* d_in, const int* in_sizes, int n_in,
                              void* d_out, int out_size) {
    const float* x        = (const float*)d_in[0];
    const float* router_w = (const float*)d_in[1];
    const float* router_b = (const float*)d_in[2];
    const float* w1       = (const float*)d_in[3];
    const float* b1       = (const float*)d_in[4];
    const float* w2       = (const float*)d_in[5];
    const float* b2       = (const float*)d_in[6];
    float* out            = (float*)d_out;
    (void)in_sizes; (void)n_in; (void)out_size;

    float* hid; cudaGetSymbolAddress((void**)&hid, g_hidden);
    float* eo;  cudaGetSymbolAddress((void**)&eo,  g_eout);
    float* xg;  cudaGetSymbolAddress((void**)&xg,  g_xg);
    float* w1t; cudaGetSymbolAddress((void**)&w1t, g_w1t);
    float* w2t; cudaGetSymbolAddress((void**)&w2t, g_w2t);

    cudaFuncSetAttribute(ffn_mma<DMODEL, FF, true >,
                         cudaFuncAttributeMaxDynamicSharedMemorySize, SMEM_TOTAL);
    cudaFuncSetAttribute(ffn_mma<FF, DMODEL, false>,
                         cudaFuncAttributeMaxDynamicSharedMemorySize, SMEM_TOTAL);

    init_kernel<<<(ROWS_MAX + 255) / 256, 256>>>();
    router_kernel<<<(T_TOK * 32 + 255) / 256, 256>>>(x, router_w, router_b);
    offsets_kernel<<<1, 1>>>();
    scatter_kernel<<<(T_TOK + 255) / 256, 256>>>();

    gather_round_kernel<<<(ROWS_MAX * (DMODEL / 4) + 255) / 256, 256>>>(x);
    // w1 [E][D][F] -> tiled w1t;  w2 [E][F][D] -> tiled w2t
    transpose_round_kernel<<<dim3(FF/32, DMODEL/32, NE), dim3(32, 8)>>>(w1, w1t, DMODEL, FF);
    transpose_round_kernel<<<dim3(DMODEL/32, FF/32, NE), dim3(32, 8)>>>(w2, w2t, FF, DMODEL);

    dim3 g1(RTILES, FF / BN);       // 136 x 8
    ffn_mma<DMODEL, FF, true><<<g1, 256, SMEM_TOTAL>>>(xg, w1t, b1, hid);

    dim3 g2(RTILES, DMODEL / BN);   // 136 x 2
    ffn_mma<FF, DMODEL, false><<<g2, 256, SMEM_TOTAL>>>(hid, w2t, b2, eo);

    combine_kernel<<<(T_TOK * 128 + 255) / 256, 256>>>(out);
}

// round 9
// speedup vs baseline: 6.1963x; 1.4613x over previous
#include <cuda_runtime.h>
#include <cuda_fp16.h>
#include <cstdint>
#include <math.h>

#define T_TOK   8192
#define DMODEL  512
#define FF      2048
#define NE      8
#define TOPK    2

#define BM 128
#define BN 256
#define ROWS_MAX (TOPK*T_TOK + NE*BM)   // 17408
#define RTILES   (ROWS_MAX / BM)        // 136

// ---------------- static device scratch -------------------------------------
// fp16 tiled layouts: [tile][kchunk(64 halves)][rows*64 halves, swizzled]
__device__ __half g_hidden[(size_t)ROWS_MAX * FF];    // [136][32][8192h]
__device__ float  g_eout[(size_t)ROWS_MAX * DMODEL];  // row-major fp32
__device__ __half g_xg[(size_t)ROWS_MAX * DMODEL];    // [136][8][8192h]
__device__ __half g_w1t[(size_t)NE * FF * DMODEL];    // [8][8][8][16384h]
__device__ __half g_w2t[(size_t)NE * DMODEL * FF];    // [8][2][32][16384h]
__device__ int   g_row_tok[ROWS_MAX];
__device__ int   g_tok_e[T_TOK * TOPK];
__device__ int   g_tok_slot[T_TOK * TOPK];
__device__ float g_tok_w[T_TOK * TOPK];
__device__ int   g_cnt[NE];
__device__ int   g_cur[NE];
__device__ int   g_pofs[NE + 1];

// ---------------- helpers ---------------------------------------------------
__device__ __forceinline__ uint32_t smem_u32(const void* p) {
    uint32_t a;
    asm("{ .reg .u64 t; cvta.to.shared.u64 t, %1; cvt.u32.u64 %0, t; }" : "=r"(a) : "l"(p));
    return a;
}
__device__ __forceinline__ void ldsm_x4(uint32_t& r0, uint32_t& r1, uint32_t& r2, uint32_t& r3,
                                        uint32_t addr) {
    asm volatile("ldmatrix.sync.aligned.m8n8.x4.shared.b16 {%0,%1,%2,%3}, [%4];"
                 : "=r"(r0), "=r"(r1), "=r"(r2), "=r"(r3) : "r"(addr));
}
__device__ __forceinline__ void mma_f16(float& c0, float& c1, float& c2, float& c3,
                                        uint32_t a0, uint32_t a1, uint32_t a2, uint32_t a3,
                                        uint32_t b0, uint32_t b1) {
    asm volatile(
        "mma.sync.aligned.m16n8k16.row.col.f32.f16.f16.f32 "
        "{%0,%1,%2,%3}, {%4,%5,%6,%7}, {%8,%9}, {%0,%1,%2,%3};"
        : "+f"(c0), "+f"(c1), "+f"(c2), "+f"(c3)
        : "r"(a0), "r"(a1), "r"(a2), "r"(a3), "r"(b0), "r"(b1));
}
#define MBARRIER_INIT(addr, cnt) \
    asm volatile("mbarrier.init.shared.b64 [%0], %1;" :: "r"(addr), "r"(cnt) : "memory")
__device__ __forceinline__ void mbar_expect(uint32_t mbar, uint32_t bytes) {
    asm volatile("mbarrier.arrive.expect_tx.shared.b64 _, [%0], %1;"
                 :: "r"(mbar), "r"(bytes) : "memory");
}
__device__ __forceinline__ void bulk_g2s(uint32_t dst, const void* src, uint32_t bytes,
                                         uint32_t mbar) {
    asm volatile("cp.async.bulk.shared::cta.global.mbarrier::complete_tx::bytes "
                 "[%0], [%1], %2, [%3];"
                 :: "r"(dst), "l"(src), "r"(bytes), "r"(mbar) : "memory");
}
__device__ __forceinline__ void mbar_wait(uint32_t mbar, uint32_t parity) {
    uint32_t done;
    asm volatile(
        "{ .reg .pred p; mbarrier.try_wait.parity.acquire.cta.shared::cta.b64 p, [%1], %2; selp.b32 %0, 1, 0, p; }"
        : "=r"(done) : "r"(mbar), "r"(parity) : "memory");
    if (!done) {
        asm volatile(
            "{ .reg .pred P1;\n"
            "WAIT_LOOP_%=:\n"
            "mbarrier.try_wait.parity.acquire.cta.shared::cta.b64 P1, [%0], %1, 0x989680;\n"
            "@P1 bra.uni WAIT_DONE_%=;\n"
            "bra.uni WAIT_LOOP_%=;\n"
            "WAIT_DONE_%=:\n}"
            :: "r"(mbar), "r"(parity) : "memory");
    }
}

// ---------------- init ------------------------------------------------------
__global__ void init_kernel() {
    int i = blockIdx.x * blockDim.x + threadIdx.x;
    if (i < NE) { g_cnt[i] = 0; g_cur[i] = 0; }
    if (i < ROWS_MAX) g_row_tok[i] = 0;
}

// ---------------- router ----------------------------------------------------
__global__ void router_kernel(const float* __restrict__ x,
                              const float* __restrict__ rw,
                              const float* __restrict__ rb) {
    int gtid = blockIdx.x * blockDim.x + threadIdx.x;
    int t = gtid >> 5, lane = gtid & 31;
    if (t >= T_TOK) return;
    const float* xr = x + (size_t)t * DMODEL;
    float acc[NE];
#pragma unroll
    for (int e = 0; e < NE; e++) acc[e] = 0.f;
    for (int d = lane; d < DMODEL; d += 32) {
        float xv = xr[d];
        const float* r = rw + d * NE;
#pragma unroll
        for (int e = 0; e < NE; e++) acc[e] = fmaf(xv, r[e], acc[e]);
    }
#pragma unroll
    for (int off = 16; off > 0; off >>= 1)
#pragma unroll
        for (int e = 0; e < NE; e++)
            acc[e] += __shfl_down_sync(0xffffffffu, acc[e], off);
    if (lane == 0) {
        float best = -1e30f, second = -1e30f;
        int b0 = 0, b1 = 0;
#pragma unroll
        for (int e = 0; e < NE; e++) {
            float l = acc[e] + rb[e];
            if (l > best)        { second = best; b1 = b0; best = l; b0 = e; }
            else if (l > second) { second = l; b1 = e; }
        }
        float w0 = 1.f / (1.f + __expf(second - best));
        g_tok_e[2*t+0] = b0;  g_tok_w[2*t+0] = w0;
        g_tok_e[2*t+1] = b1;  g_tok_w[2*t+1] = 1.f - w0;
        atomicAdd(&g_cnt[b0], 1);
        atomicAdd(&g_cnt[b1], 1);
    }
}

// ---------------- offsets ---------------------------------------------------
__global__ void offsets_kernel() {
    int o = 0;
    for (int e = 0; e < NE; e++) {
        g_pofs[e] = o;
        o += ((g_cnt[e] + BM - 1) / BM) * BM;
    }
    g_pofs[NE] = o;
}

// ---------------- scatter ---------------------------------------------------
__global__ void scatter_kernel() {
    int t = blockIdx.x * blockDim.x + threadIdx.x;
    if (t >= T_TOK) return;
#pragma unroll
    for (int k = 0; k < TOPK; k++) {
        int e = g_tok_e[2*t+k];
        int pos = g_pofs[e] + atomicAdd(&g_cur[e], 1);
        g_row_tok[pos] = t;
        g_tok_slot[2*t+k] = pos;
    }
}

// ---------------- gather x -> fp16 tiled-swizzled ---------------------------
// block [rtile][kch(64h)][8192h]; elem (r,k): r*64 + (((k&63)>>3) ^ (r&7))*8 + (k&7)
__global__ void gather_h_kernel(const float* __restrict__ x) {
    int id = blockIdx.x * blockDim.x + threadIdx.x;   // one 8-half unit each
    const int UNITS = DMODEL / 8;                      // 64
    if (id >= ROWS_MAX * UNITS) return;
    int s  = id / UNITS;
    int un = id % UNITS;
    int kch = un >> 3;
    int u   = un & 7;
    int r   = s & (BM - 1);
    int tok = g_row_tok[s];
    const float4* src = (const float4*)(x + (size_t)tok * DMODEL + un * 8);
    float4 v0 = src[0], v1 = src[1];
    __half2 h[4];
    h[0] = __floats2half2_rn(v0.x, v0.y);
    h[1] = __floats2half2_rn(v0.z, v0.w);
    h[2] = __floats2half2_rn(v1.x, v1.y);
    h[3] = __floats2half2_rn(v1.z, v1.w);
    size_t base = ((size_t)(s >> 7) * (DMODEL / 64) + kch) * 8192;
    *(uint4*)((__half*)g_xg + base + r * 64 + ((u ^ (r & 7)) << 3)) = *(uint4*)h;
}

// ---------------- weight transpose -> fp16 tiled-swizzled -------------------
// src [E][R][C] (R=k, C=n) -> dst [E][C/256][R/64][16384h]
// elem (n,k): (n&255)*64 + ((((k&63)>>3) ^ (n&7))<<3) + (k&7)
__global__ void transpose_h_kernel(const float* __restrict__ src, __half* __restrict__ dst,
                                   int R, int C) {
    __shared__ float tile[32][33];
    int e = blockIdx.z;
    int c0 = blockIdx.x * 32, r0 = blockIdx.y * 32;   // c=n, r=k
    const float* s = src + (size_t)e * R * C;
    // threads: x=0..31 (n col), y=0..3 (k group)
    for (int kk = threadIdx.y; kk < 32; kk += 4)
        tile[kk][threadIdx.x] = s[(size_t)(r0 + kk) * C + c0 + threadIdx.x];
    __syncthreads();
    int n  = c0 + threadIdx.x;
    int kg = threadIdx.y;                              // 0..3, 8 k each
    int kbase = r0 + kg * 8;
    __half2 h[4];
#pragma unroll
    for (int j = 0; j < 4; j++)
        h[j] = __floats2half2_rn(tile[kg * 8 + 2*j][threadIdx.x],
                                 tile[kg * 8 + 2*j + 1][threadIdx.x]);
    int nn = n & 255;
    int u  = (kbase & 63) >> 3;
    size_t base = (((size_t)e * (C >> 8) + (n >> 8)) * (R >> 6) + (kbase >> 6)) * 16384;
    *(uint4*)(dst + base + nn * 64 + ((u ^ (nn & 7)) << 3)) = *(uint4*)h;
}

// ---------------- grouped fp16 mma.sync GEMM, bulk-copy pipeline ------------
// A: [rtile][KD/64][8192h swz], B: [E...][ntile][KD/64][16384h swz]
#define A_STAGE 16384
#define B_STAGE 32768
#define STAGE_BYTES (A_STAGE + B_STAGE)            // 49152
#define SM_MB (3 * STAGE_BYTES)                    // 147456
#define SMEM_TOTAL (SM_MB + 64)

template<int KD, int NTOT, bool TILED_OUT>
__global__ __launch_bounds__(256, 1)
void ffn_mma(const __half* __restrict__ Atiled,
             const __half* __restrict__ Wt,
             const float* __restrict__ bias,
             void* __restrict__ OutV) {
    extern __shared__ __align__(128) char smem[];
    const int tid  = threadIdx.x;
    const int wid  = tid >> 5;
    const int lane = tid & 31;
    const int qid  = lane >> 2;
    const int rid  = lane & 3;
    const int wm   = wid >> 2;
    const int wn   = wid & 3;

    const int r0 = blockIdx.x * BM;
    if (r0 >= g_pofs[NE]) return;
    int e = 0;
    while (r0 >= g_pofs[e + 1]) e++;

    const uint32_t sb = smem_u32(smem);
    if (tid == 0) {
        MBARRIER_INIT(sb + SM_MB,      1);
        MBARRIER_INIT(sb + SM_MB + 8,  1);
        MBARRIER_INIT(sb + SM_MB + 16, 1);
    }
    __syncthreads();

    const int NCH = KD / 64;
    const __half* Asrc = Atiled + (size_t)blockIdx.x * NCH * 8192;
    const __half* Bsrc = Wt + (((size_t)e * (NTOT / 256) + blockIdx.y) * NCH) * 16384;
    const int n0 = blockIdx.y * BN;

    // ldmatrix lane geometry (swizzled): byte addr = row*128 + ((u ^ (row&7))<<4)
    const int sel = lane >> 3, lr = lane & 7;
    uint32_t a_base[4], a_s7[4];
#pragma unroll
    for (int mt = 0; mt < 4; mt++) {
        int arow = wm * 64 + mt * 16 + (sel & 1) * 8 + lr;
        a_base[mt] = (uint32_t)(arow * 128);
        a_s7[mt]   = (uint32_t)(arow & 7);
    }
    const uint32_t ua0 = (uint32_t)(sel >> 1);
    uint32_t b_base[4], b_s7[4];
#pragma unroll
    for (int g = 0; g < 4; g++) {
        int brow = wn * 64 + (2 * g + (sel >> 1)) * 8 + lr;
        b_base[g] = (uint32_t)(A_STAGE + brow * 128);
        b_s7[g]   = (uint32_t)(brow & 7);
    }
    const uint32_t ub0 = (uint32_t)(sel & 1);

    float acc[4][8][4];
#pragma unroll
    for (int i = 0; i < 4; i++)
#pragma unroll
        for (int j = 0; j < 8; j++)
#pragma unroll
            for (int k = 0; k < 4; k++) acc[i][j][k] = 0.f;

    const int NIT = NCH;

    if (tid == 0) {
#pragma unroll
        for (int s = 0; s < 2; s++) {
            mbar_expect(sb + SM_MB + 8 * s, STAGE_BYTES);
            bulk_g2s(sb + s * STAGE_BYTES,           Asrc + (size_t)s * 8192,  A_STAGE,
                     sb + SM_MB + 8 * s);
            bulk_g2s(sb + s * STAGE_BYTES + A_STAGE, Bsrc + (size_t)s * 16384, B_STAGE,
                     sb + SM_MB + 8 * s);
        }
    }

    for (int it = 0; it < NIT; it++) {
        int stage = it % 3;
        if (it + 2 < NIT && tid == 0) {
            int s2 = (it + 2) % 3;
            mbar_expect(sb + SM_MB + 8 * s2, STAGE_BYTES);
            bulk_g2s(sb + s2 * STAGE_BYTES,           Asrc + (size_t)(it + 2) * 8192,  A_STAGE,
                     sb + SM_MB + 8 * s2);
            bulk_g2s(sb + s2 * STAGE_BYTES + A_STAGE, Bsrc + (size_t)(it + 2) * 16384, B_STAGE,
                     sb + SM_MB + 8 * s2);
        }
        mbar_wait(sb + SM_MB + 8 * stage, (it / 3) & 1);

        const uint32_t sbS = sb + stage * STAGE_BYTES;
#pragma unroll
        for (int ks = 0; ks < 4; ks++) {   // k16 per step, 64 halves per iter
            uint32_t a[4][4], b[8][2];
#pragma unroll
            for (int mt = 0; mt < 4; mt++)
                ldsm_x4(a[mt][0], a[mt][1], a[mt][2], a[mt][3],
                        sbS + a_base[mt] + (((ua0 + 2 * ks) ^ a_s7[mt]) << 4));
#pragma unroll
            for (int g = 0; g < 4; g++)
                ldsm_x4(b[2*g][0], b[2*g][1], b[2*g+1][0], b[2*g+1][1],
                        sbS + b_base[g] + (((ub0 + 2 * ks) ^ b_s7[g]) << 4));
#pragma unroll
            for (int mt = 0; mt < 4; mt++)
#pragma unroll
                for (int nt = 0; nt < 8; nt++)
                    mma_f16(acc[mt][nt][0], acc[mt][nt][1], acc[mt][nt][2], acc[mt][nt][3],
                            a[mt][0], a[mt][1], a[mt][2], a[mt][3],
                            b[nt][0], b[nt][1]);
        }
        __syncthreads();
    }

    const float* be = bias + (size_t)e * NTOT + n0;
#pragma unroll
    for (int mt = 0; mt < 4; mt++) {
        int rowl = wm * 64 + mt * 16 + qid;
#pragma unroll
        for (int nt = 0; nt < 8; nt++) {
            int col = wn * 64 + nt * 8 + 2 * rid;
            float2 bv = *(const float2*)(be + col);
            float2 v0, v1;
            v0.x = acc[mt][nt][0] + bv.x;
            v0.y = acc[mt][nt][1] + bv.y;
            v1.x = acc[mt][nt][2] + bv.x;
            v1.y = acc[mt][nt][3] + bv.y;
            if (TILED_OUT) {
                // relu + fp16 + tiled-swizzled store (hidden, GEMM2's A layout)
                __half* Out = (__half*)OutV;
                __half2 h0 = __floats2half2_rn(fmaxf(v0.x, 0.f), fmaxf(v0.y, 0.f));
                __half2 h1 = __floats2half2_rn(fmaxf(v1.x, 0.f), fmaxf(v1.y, 0.f));
                int n = n0 + col;
                size_t base = ((size_t)blockIdx.x * (NTOT >> 6) + (n >> 6)) * 8192;
                int u = (n & 63) >> 3, off = n & 7;
                int r0l = rowl, r1l = rowl + 8;
                *(__half2*)(Out + base + r0l * 64 + ((u ^ (r0l & 7)) << 3) + off) = h0;
                *(__half2*)(Out + base + r1l * 64 + ((u ^ (r1l & 7)) << 3) + off) = h1;
            } else {
                float* Out = (float*)OutV;
                int row = r0 + rowl;
                *(float2*)(Out + (size_t)row * NTOT + n0 + col)       = v0;
                *(float2*)(Out + (size_t)(row + 8) * NTOT + n0 + col) = v1;
            }
        }
    }
}

// ---------------- combine ---------------------------------------------------
__global__ void combine_kernel(float* __restrict__ out) {
    int gid = blockIdx.x * blockDim.x + threadIdx.x;
    int t = gid >> 7;
    int j = (gid & 127) * 4;
    if (t >= T_TOK) return;
    int s0 = g_tok_slot[2*t], s1 = g_tok_slot[2*t+1];
    float w0 = g_tok_w[2*t], w1 = g_tok_w[2*t+1];
    float4 a = *(const float4*)(g_eout + (size_t)s0 * DMODEL + j);
    float4 b = *(const float4*)(g_eout + (size_t)s1 * DMODEL + j);
    float4 o;
    o.x = w0 * a.x + w1 * b.x;
    o.y = w0 * a.y + w1 * b.y;
    o.z = w0 * a.z + w1 * b.z;
    o.w = w0 * a.w + w1 * b.w;
    *(float4*)(out + (size_t)t * DMODEL + j) = o;
}

// ---------------------------------------------------------------------------
extern "C" void kernel_launch(void* const* d_in, const int* in_sizes, int n_in,
                              void* d_out, int out_size) {
    const float* x        = (const float*)d_in[0];
    const float* router_w = (const float*)d_in[1];
    const float* router_b = (const float*)d_in[2];
    const float* w1       = (const float*)d_in[3];
    const float* b1       = (const float*)d_in[4];
    const float* w2       = (const float*)d_in[5];
    const float* b2       = (const float*)d_in[6];
    float* out            = (float*)d_out;
    (void)in_sizes; (void)n_in; (void)out_size;

    __half* hid; cudaGetSymbolAddress((void**)&hid, g_hidden);
    float*  eo;  cudaGetSymbolAddress((void**)&eo,  g_eout);
    __half* xg;  cudaGetSymbolAddress((void**)&xg,  g_xg);
    __half* w1t; cudaGetSymbolAddress((void**)&w1t, g_w1t);
    __half* w2t; cudaGetSymbolAddress((void**)&w2t, g_w2t);

    cudaFuncSetAttribute(ffn_mma<DMODEL, FF, true >,
                         cudaFuncAttributeMaxDynamicSharedMemorySize, SMEM_TOTAL);
    cudaFuncSetAttribute(ffn_mma<FF, DMODEL, false>,
                         cudaFuncAttributeMaxDynamicSharedMemorySize, SMEM_TOTAL);

    init_kernel<<<(ROWS_MAX + 255) / 256, 256>>>();
    router_kernel<<<(T_TOK * 32 + 255) / 256, 256>>>(x, router_w, router_b);
    offsets_kernel<<<1, 1>>>();
    scatter_kernel<<<(T_TOK + 255) / 256, 256>>>();

    gather_h_kernel<<<(ROWS_MAX * (DMODEL / 8) + 255) / 256, 256>>>(x);
    // w1 [E][D][F] -> tiled fp16 w1t;  w2 [E][F][D] -> tiled fp16 w2t
    transpose_h_kernel<<<dim3(FF/32, DMODEL/32, NE), dim3(32, 4)>>>(w1, w1t, DMODEL, FF);
    transpose_h_kernel<<<dim3(DMODEL/32, FF/32, NE), dim3(32, 4)>>>(w2, w2t, FF, DMODEL);

    dim3 g1(RTILES, FF / BN);       // 136 x 8
    ffn_mma<DMODEL, FF, true><<<g1, 256, SMEM_TOTAL>>>(xg, w1t, b1, hid);

    dim3 g2(RTILES, DMODEL / BN);   // 136 x 2
    ffn_mma<FF, DMODEL, false><<<g2, 256, SMEM_TOTAL>>>(hid, w2t, b2, eo);

    combine_kernel<<<(T_TOK * 128 + 255) / 256, 256>>>(out);
}

// round 10
// speedup vs baseline: 6.2857x; 1.0144x over previous
#include <cuda_runtime.h>
#include <cuda_fp16.h>
#include <cstdint>
#include <math.h>

#define T_TOK   8192
#define DMODEL  512
#define FF      2048
#define NE      8
#define TOPK    2

#define BM 128
#define BN 256
#define ROWS_MAX (TOPK*T_TOK + NE*BM)   // 17408
#define RTILES   (ROWS_MAX / BM)        // 136

// ---------------- static device scratch -------------------------------------
__device__ __half g_hidden[(size_t)ROWS_MAX * FF];    // [136][32][8192h]
__device__ float  g_eout[(size_t)ROWS_MAX * DMODEL];  // row-major fp32
__device__ __half g_xg[(size_t)ROWS_MAX * DMODEL];    // [136][8][8192h]
__device__ __half g_w1t[(size_t)NE * FF * DMODEL];    // [8][8][8][16384h]
__device__ __half g_w2t[(size_t)NE * DMODEL * FF];    // [8][2][32][16384h]
__device__ int   g_row_tok[ROWS_MAX];
__device__ int   g_tok_e[T_TOK * TOPK];
__device__ int   g_tok_slot[T_TOK * TOPK];
__device__ float g_tok_w[T_TOK * TOPK];
__device__ int   g_cnt[NE];
__device__ int   g_cur[NE];
__device__ int   g_pofs[NE + 1];

// ---------------- helpers ---------------------------------------------------
__device__ __forceinline__ uint32_t smem_u32(const void* p) {
    uint32_t a;
    asm("{ .reg .u64 t; cvta.to.shared.u64 t, %1; cvt.u32.u64 %0, t; }" : "=r"(a) : "l"(p));
    return a;
}
__device__ __forceinline__ void ldsm_x4(uint32_t& r0, uint32_t& r1, uint32_t& r2, uint32_t& r3,
                                        uint32_t addr) {
    asm volatile("ldmatrix.sync.aligned.m8n8.x4.shared.b16 {%0,%1,%2,%3}, [%4];"
                 : "=r"(r0), "=r"(r1), "=r"(r2), "=r"(r3) : "r"(addr));
}
__device__ __forceinline__ void mma_f16(float& c0, float& c1, float& c2, float& c3,
                                        uint32_t a0, uint32_t a1, uint32_t a2, uint32_t a3,
                                        uint32_t b0, uint32_t b1) {
    asm volatile(
        "mma.sync.aligned.m16n8k16.row.col.f32.f16.f16.f32 "
        "{%0,%1,%2,%3}, {%4,%5,%6,%7}, {%8,%9}, {%0,%1,%2,%3};"
        : "+f"(c0), "+f"(c1), "+f"(c2), "+f"(c3)
        : "r"(a0), "r"(a1), "r"(a2), "r"(a3), "r"(b0), "r"(b1));
}
#define MBARRIER_INIT(addr, cnt) \
    asm volatile("mbarrier.init.shared.b64 [%0], %1;" :: "r"(addr), "r"(cnt) : "memory")
__device__ __forceinline__ void mbar_expect(uint32_t mbar, uint32_t bytes) {
    asm volatile("mbarrier.arrive.expect_tx.shared.b64 _, [%0], %1;"
                 :: "r"(mbar), "r"(bytes) : "memory");
}
__device__ __forceinline__ void bulk_g2s(uint32_t dst, const void* src, uint32_t bytes,
                                         uint32_t mbar) {
    asm volatile("cp.async.bulk.shared::cta.global.mbarrier::complete_tx::bytes "
                 "[%0], [%1], %2, [%3];"
                 :: "r"(dst), "l"(src), "r"(bytes), "r"(mbar) : "memory");
}
__device__ __forceinline__ void mbar_wait(uint32_t mbar, uint32_t parity) {
    uint32_t done;
    asm volatile(
        "{ .reg .pred p; mbarrier.try_wait.parity.acquire.cta.shared::cta.b64 p, [%1], %2; selp.b32 %0, 1, 0, p; }"
        : "=r"(done) : "r"(mbar), "r"(parity) : "memory");
    if (!done) {
        asm volatile(
            "{ .reg .pred P1;\n"
            "WAIT_LOOP_%=:\n"
            "mbarrier.try_wait.parity.acquire.cta.shared::cta.b64 P1, [%0], %1, 0x989680;\n"
            "@P1 bra.uni WAIT_DONE_%=;\n"
            "bra.uni WAIT_LOOP_%=;\n"
            "WAIT_DONE_%=:\n}"
            :: "r"(mbar), "r"(parity) : "memory");
    }
}

// ---------------- init ------------------------------------------------------
__global__ void init_kernel() {
    int i = blockIdx.x * blockDim.x + threadIdx.x;
    if (i < NE) { g_cnt[i] = 0; g_cur[i] = 0; }
    if (i < ROWS_MAX) g_row_tok[i] = 0;
}

// ---------------- router ----------------------------------------------------
__global__ void router_kernel(const float* __restrict__ x,
                              const float* __restrict__ rw,
                              const float* __restrict__ rb) {
    int gtid = blockIdx.x * blockDim.x + threadIdx.x;
    int t = gtid >> 5, lane = gtid & 31;
    if (t >= T_TOK) return;
    const float* xr = x + (size_t)t * DMODEL;
    float acc[NE];
#pragma unroll
    for (int e = 0; e < NE; e++) acc[e] = 0.f;
    for (int d = lane; d < DMODEL; d += 32) {
        float xv = xr[d];
        const float* r = rw + d * NE;
#pragma unroll
        for (int e = 0; e < NE; e++) acc[e] = fmaf(xv, r[e], acc[e]);
    }
#pragma unroll
    for (int off = 16; off > 0; off >>= 1)
#pragma unroll
        for (int e = 0; e < NE; e++)
            acc[e] += __shfl_down_sync(0xffffffffu, acc[e], off);
    if (lane == 0) {
        float best = -1e30f, second = -1e30f;
        int b0 = 0, b1 = 0;
#pragma unroll
        for (int e = 0; e < NE; e++) {
            float l = acc[e] + rb[e];
            if (l > best)        { second = best; b1 = b0; best = l; b0 = e; }
            else if (l > second) { second = l; b1 = e; }
        }
        float w0 = 1.f / (1.f + __expf(second - best));
        g_tok_e[2*t+0] = b0;  g_tok_w[2*t+0] = w0;
        g_tok_e[2*t+1] = b1;  g_tok_w[2*t+1] = 1.f - w0;
        atomicAdd(&g_cnt[b0], 1);
        atomicAdd(&g_cnt[b1], 1);
    }
}

// ---------------- offsets ---------------------------------------------------
__global__ void offsets_kernel() {
    int o = 0;
    for (int e = 0; e < NE; e++) {
        g_pofs[e] = o;
        o += ((g_cnt[e] + BM - 1) / BM) * BM;
    }
    g_pofs[NE] = o;
}

// ---------------- scatter ---------------------------------------------------
__global__ void scatter_kernel() {
    int t = blockIdx.x * blockDim.x + threadIdx.x;
    if (t >= T_TOK) return;
#pragma unroll
    for (int k = 0; k < TOPK; k++) {
        int e = g_tok_e[2*t+k];
        int pos = g_pofs[e] + atomicAdd(&g_cur[e], 1);
        g_row_tok[pos] = t;
        g_tok_slot[2*t+k] = pos;
    }
}

// ---------------- gather x -> fp16 tiled-swizzled ---------------------------
__global__ void gather_h_kernel(const float* __restrict__ x) {
    int id = blockIdx.x * blockDim.x + threadIdx.x;
    const int UNITS = DMODEL / 8;                      // 64
    if (id >= ROWS_MAX * UNITS) return;
    int s  = id / UNITS;
    int un = id % UNITS;
    int kch = un >> 3;
    int u   = un & 7;
    int r   = s & (BM - 1);
    int tok = g_row_tok[s];
    const float4* src = (const float4*)(x + (size_t)tok * DMODEL + un * 8);
    float4 v0 = src[0], v1 = src[1];
    __half2 h[4];
    h[0] = __floats2half2_rn(v0.x, v0.y);
    h[1] = __floats2half2_rn(v0.z, v0.w);
    h[2] = __floats2half2_rn(v1.x, v1.y);
    h[3] = __floats2half2_rn(v1.z, v1.w);
    size_t base = ((size_t)(s >> 7) * (DMODEL / 64) + kch) * 8192;
    *(uint4*)((__half*)g_xg + base + r * 64 + ((u ^ (r & 7)) << 3)) = *(uint4*)h;
}

// ---------------- weight transpose -> fp16 tiled-swizzled -------------------
__global__ void transpose_h_kernel(const float* __restrict__ src, __half* __restrict__ dst,
                                   int R, int C) {
    __shared__ float tile[32][33];
    int e = blockIdx.z;
    int c0 = blockIdx.x * 32, r0 = blockIdx.y * 32;   // c=n, r=k
    const float* s = src + (size_t)e * R * C;
    for (int kk = threadIdx.y; kk < 32; kk += 4)
        tile[kk][threadIdx.x] = s[(size_t)(r0 + kk) * C + c0 + threadIdx.x];
    __syncthreads();
    int n  = c0 + threadIdx.x;
    int kg = threadIdx.y;
    int kbase = r0 + kg * 8;
    __half2 h[4];
#pragma unroll
    for (int j = 0; j < 4; j++)
        h[j] = __floats2half2_rn(tile[kg * 8 + 2*j][threadIdx.x],
                                 tile[kg * 8 + 2*j + 1][threadIdx.x]);
    int nn = n & 255;
    int u  = (kbase & 63) >> 3;
    size_t base = (((size_t)e * (C >> 8) + (n >> 8)) * (R >> 6) + (kbase >> 6)) * 16384;
    *(uint4*)(dst + base + nn * 64 + ((u ^ (nn & 7)) << 3)) = *(uint4*)h;
}

// ---------------- grouped fp16 mma.sync GEMM, 4-stage bulk pipeline ---------
#define A_STAGE 16384
#define B_STAGE 32768
#define STAGE_BYTES (A_STAGE + B_STAGE)            // 49152
#define NSTAGE 4
#define SM_MB (NSTAGE * STAGE_BYTES)               // 196608
#define SMEM_TOTAL (SM_MB + 64)

template<int KD, int NTOT, bool TILED_OUT>
__global__ __launch_bounds__(256, 1)
void ffn_mma(const __half* __restrict__ Atiled,
             const __half* __restrict__ Wt,
             const float* __restrict__ bias,
             void* __restrict__ OutV) {
    extern __shared__ __align__(128) char smem[];
    const int tid  = threadIdx.x;
    const int wid  = tid >> 5;
    const int lane = tid & 31;
    const int qid  = lane >> 2;
    const int rid  = lane & 3;
    const int wm   = wid >> 2;
    const int wn   = wid & 3;

    const int r0 = blockIdx.x * BM;
    if (r0 >= g_pofs[NE]) return;
    int e = 0;
    while (r0 >= g_pofs[e + 1]) e++;

    const uint32_t sb = smem_u32(smem);
    if (tid == 0) {
#pragma unroll
        for (int s = 0; s < NSTAGE; s++)
            MBARRIER_INIT(sb + SM_MB + 8 * s, 1);
    }
    __syncthreads();

    const int NCH = KD / 64;
    const __half* Asrc = Atiled + (size_t)blockIdx.x * NCH * 8192;
    const __half* Bsrc = Wt + (((size_t)e * (NTOT / 256) + blockIdx.y) * NCH) * 16384;
    const int n0 = blockIdx.y * BN;

    const int sel = lane >> 3, lr = lane & 7;
    uint32_t a_base[4], a_s7[4];
#pragma unroll
    for (int mt = 0; mt < 4; mt++) {
        int arow = wm * 64 + mt * 16 + (sel & 1) * 8 + lr;
        a_base[mt] = (uint32_t)(arow * 128);
        a_s7[mt]   = (uint32_t)(arow & 7);
    }
    const uint32_t ua0 = (uint32_t)(sel >> 1);
    uint32_t b_base[4], b_s7[4];
#pragma unroll
    for (int g = 0; g < 4; g++) {
        int brow = wn * 64 + (2 * g + (sel >> 1)) * 8 + lr;
        b_base[g] = (uint32_t)(A_STAGE + brow * 128);
        b_s7[g]   = (uint32_t)(brow & 7);
    }
    const uint32_t ub0 = (uint32_t)(sel & 1);

    float acc[4][8][4];
#pragma unroll
    for (int i = 0; i < 4; i++)
#pragma unroll
        for (int j = 0; j < 8; j++)
#pragma unroll
            for (int k = 0; k < 4; k++) acc[i][j][k] = 0.f;

    const int NIT = NCH;
    const int PRO = (NIT < NSTAGE - 1) ? NIT : NSTAGE - 1;   // 3 in-flight

    if (tid == 0) {
        for (int s = 0; s < PRO; s++) {
            mbar_expect(sb + SM_MB + 8 * s, STAGE_BYTES);
            bulk_g2s(sb + s * STAGE_BYTES,           Asrc + (size_t)s * 8192,  A_STAGE,
                     sb + SM_MB + 8 * s);
            bulk_g2s(sb + s * STAGE_BYTES + A_STAGE, Bsrc + (size_t)s * 16384, B_STAGE,
                     sb + SM_MB + 8 * s);
        }
    }

    for (int it = 0; it < NIT; it++) {
        int stage = it % NSTAGE;
        if (it + PRO < NIT && tid == 0) {
            int s2 = (it + PRO) % NSTAGE;
            mbar_expect(sb + SM_MB + 8 * s2, STAGE_BYTES);
            bulk_g2s(sb + s2 * STAGE_BYTES,           Asrc + (size_t)(it + PRO) * 8192,  A_STAGE,
                     sb + SM_MB + 8 * s2);
            bulk_g2s(sb + s2 * STAGE_BYTES + A_STAGE, Bsrc + (size_t)(it + PRO) * 16384, B_STAGE,
                     sb + SM_MB + 8 * s2);
        }
        mbar_wait(sb + SM_MB + 8 * stage, (it / NSTAGE) & 1);

        const uint32_t sbS = sb + stage * STAGE_BYTES;
#pragma unroll
        for (int ks = 0; ks < 4; ks++) {
            uint32_t a[4][4], b[8][2];
#pragma unroll
            for (int mt = 0; mt < 4; mt++)
                ldsm_x4(a[mt][0], a[mt][1], a[mt][2], a[mt][3],
                        sbS + a_base[mt] + (((ua0 + 2 * ks) ^ a_s7[mt]) << 4));
#pragma unroll
            for (int g = 0; g < 4; g++)
                ldsm_x4(b[2*g][0], b[2*g][1], b[2*g+1][0], b[2*g+1][1],
                        sbS + b_base[g] + (((ub0 + 2 * ks) ^ b_s7[g]) << 4));
#pragma unroll
            for (int mt = 0; mt < 4; mt++)
#pragma unroll
                for (int nt = 0; nt < 8; nt++)
                    mma_f16(acc[mt][nt][0], acc[mt][nt][1], acc[mt][nt][2], acc[mt][nt][3],
                            a[mt][0], a[mt][1], a[mt][2], a[mt][3],
                            b[nt][0], b[nt][1]);
        }
        __syncthreads();
    }

    const float* be = bias + (size_t)e * NTOT + n0;
#pragma unroll
    for (int mt = 0; mt < 4; mt++) {
        int rowl = wm * 64 + mt * 16 + qid;
#pragma unroll
        for (int nt = 0; nt < 8; nt++) {
            int col = wn * 64 + nt * 8 + 2 * rid;
            float2 bv = *(const float2*)(be + col);
            float2 v0, v1;
            v0.x = acc[mt][nt][0] + bv.x;
            v0.y = acc[mt][nt][1] + bv.y;
            v1.x = acc[mt][nt][2] + bv.x;
            v1.y = acc[mt][nt][3] + bv.y;
            if (TILED_OUT) {
                __half* Out = (__half*)OutV;
                __half2 h0 = __floats2half2_rn(fmaxf(v0.x, 0.f), fmaxf(v0.y, 0.f));
                __half2 h1 = __floats2half2_rn(fmaxf(v1.x, 0.f), fmaxf(v1.y, 0.f));
                int n = n0 + col;
                size_t base = ((size_t)blockIdx.x * (NTOT >> 6) + (n >> 6)) * 8192;
                int u = (n & 63) >> 3, off = n & 7;
                int r0l = rowl, r1l = rowl + 8;
                *(__half2*)(Out + base + r0l * 64 + ((u ^ (r0l & 7)) << 3) + off) = h0;
                *(__half2*)(Out + base + r1l * 64 + ((u ^ (r1l & 7)) << 3) + off) = h1;
            } else {
                float* Out = (float*)OutV;
                int row = r0 + rowl;
                *(float2*)(Out + (size_t)row * NTOT + n0 + col)       = v0;
                *(float2*)(Out + (size_t)(row + 8) * NTOT + n0 + col) = v1;
            }
        }
    }
}

// ---------------- combine ---------------------------------------------------
__global__ void combine_kernel(float* __restrict__ out) {
    int gid = blockIdx.x * blockDim.x + threadIdx.x;
    int t = gid >> 7;
    int j = (gid & 127) * 4;
    if (t >= T_TOK) return;
    int s0 = g_tok_slot[2*t], s1 = g_tok_slot[2*t+1];
    float w0 = g_tok_w[2*t], w1 = g_tok_w[2*t+1];
    float4 a = *(const float4*)(g_eout + (size_t)s0 * DMODEL + j);
    float4 b = *(const float4*)(g_eout + (size_t)s1 * DMODEL + j);
    float4 o;
    o.x = w0 * a.x + w1 * b.x;
    o.y = w0 * a.y + w1 * b.y;
    o.z = w0 * a.z + w1 * b.z;
    o.w = w0 * a.w + w1 * b.w;
    *(float4*)(out + (size_t)t * DMODEL + j) = o;
}

// ---------------------------------------------------------------------------
extern "C" void kernel_launch(void* const* d_in, const int* in_sizes, int n_in,
                              void* d_out, int out_size) {
    const float* x        = (const float*)d_in[0];
    const float* router_w = (const float*)d_in[1];
    const float* router_b = (const float*)d_in[2];
    const float* w1       = (const float*)d_in[3];
    const float* b1       = (const float*)d_in[4];
    const float* w2       = (const float*)d_in[5];
    const float* b2       = (const float*)d_in[6];
    float* out            = (float*)d_out;
    (void)in_sizes; (void)n_in; (void)out_size;

    __half* hid; cudaGetSymbolAddress((void**)&hid, g_hidden);
    float*  eo;  cudaGetSymbolAddress((void**)&eo,  g_eout);
    __half* xg;  cudaGetSymbolAddress((void**)&xg,  g_xg);
    __half* w1t; cudaGetSymbolAddress((void**)&w1t, g_w1t);
    __half* w2t; cudaGetSymbolAddress((void**)&w2t, g_w2t);

    cudaFuncSetAttribute(ffn_mma<DMODEL, FF, true >,
                         cudaFuncAttributeMaxDynamicSharedMemorySize, SMEM_TOTAL);
    cudaFuncSetAttribute(ffn_mma<FF, DMODEL, false>,
                         cudaFuncAttributeMaxDynamicSharedMemorySize, SMEM_TOTAL);

    init_kernel<<<(ROWS_MAX + 255) / 256, 256>>>();
    router_kernel<<<(T_TOK * 32 + 255) / 256, 256>>>(x, router_w, router_b);
    offsets_kernel<<<1, 1>>>();
    scatter_kernel<<<(T_TOK + 255) / 256, 256>>>();

    gather_h_kernel<<<(ROWS_MAX * (DMODEL / 8) + 255) / 256, 256>>>(x);
    transpose_h_kernel<<<dim3(FF/32, DMODEL/32, NE), dim3(32, 4)>>>(w1, w1t, DMODEL, FF);
    transpose_h_kernel<<<dim3(DMODEL/32, FF/32, NE), dim3(32, 4)>>>(w2, w2t, FF, DMODEL);

    dim3 g1(RTILES, FF / BN);       // 136 x 8
    ffn_mma<DMODEL, FF, true><<<g1, 256, SMEM_TOTAL>>>(xg, w1t, b1, hid);

    dim3 g2(RTILES, DMODEL / BN);   // 136 x 2
    ffn_mma<FF, DMODEL, false><<<g2, 256, SMEM_TOTAL>>>(hid, w2t, b2, eo);

    combine_kernel<<<(T_TOK * 128 + 255) / 256, 256>>>(out);
}